// round 2
// baseline (speedup 1.0000x reference)
#include <cuda_runtime.h>
#include <math.h>

// Problem dims
#define DD    1024      // model dim D
#define EE    16        // experts
#define SS    16        // slots per expert
#define ESL   256       // E*S
#define BB    64        // batch
#define NT    256       // tokens N
#define BNR   16384     // B*N rows
#define HH    256       // hidden H

// ---------------- scratch (device globals; no allocation allowed) ------------
__device__ float g_xn[(long long)BNR * DD];              // LayerNorm output [B*N, D]
__device__ float g_rnorm[BNR];                           // scale / ||xn|| per row
__device__ float g_muuT[ESL * DD];                       // mu_unit transposed [ES, D]
__device__ float g_logits[(long long)BNR * ESL];         // [B*N, ES]
__device__ float g_dispT[(long long)BB * ESL * NT];      // dispatch^T [b][es][n]
__device__ float g_combine[(long long)BNR * ESL];        // [b][n][es]
__device__ float g_slotin[(long long)EE * BB * SS * DD]; // [e][b*S+s][d]
__device__ float g_h[(long long)EE * BB * SS * HH];      // [e][b*S+s][h]
__device__ float g_slotout[(long long)BB * ESL * DD];    // [b][es][d]

// ---------------- reductions (256-thread blocks) -----------------------------
__device__ __forceinline__ float blockReduceSum256(float v, float* sh) {
    #pragma unroll
    for (int o = 16; o > 0; o >>= 1) v += __shfl_down_sync(0xffffffffu, v, o);
    int lane = threadIdx.x & 31, w = threadIdx.x >> 5;
    if (lane == 0) sh[w] = v;
    __syncthreads();
    if (w == 0) {
        float t = (lane < 8) ? sh[lane] : 0.0f;
        #pragma unroll
        for (int o = 4; o > 0; o >>= 1) t += __shfl_down_sync(0xffu, t, o);
        if (lane == 0) sh[0] = t;
    }
    __syncthreads();
    float r = sh[0];
    __syncthreads();
    return r;
}

__device__ __forceinline__ float blockReduceMax256(float v, float* sh) {
    #pragma unroll
    for (int o = 16; o > 0; o >>= 1) v = fmaxf(v, __shfl_down_sync(0xffffffffu, v, o));
    int lane = threadIdx.x & 31, w = threadIdx.x >> 5;
    if (lane == 0) sh[w] = v;
    __syncthreads();
    if (w == 0) {
        float t = (lane < 8) ? sh[lane] : -INFINITY;
        #pragma unroll
        for (int o = 4; o > 0; o >>= 1) t = fmaxf(t, __shfl_down_sync(0xffu, t, o));
        if (lane == 0) sh[0] = t;
    }
    __syncthreads();
    float r = sh[0];
    __syncthreads();
    return r;
}

__device__ __forceinline__ float gelu_f(float v) {
    return 0.5f * v * (1.0f + erff(v * 0.70710678118654752f));
}

// ---------------- kernel 1: LayerNorm + row inv-norm -------------------------
__global__ void ln_kernel(const float* __restrict__ x,
                          const float* __restrict__ gamma,
                          const float* __restrict__ beta,
                          const float* __restrict__ scale) {
    __shared__ float sh[8];
    int row = blockIdx.x;
    const float4* xr = (const float4*)(x + (long long)row * DD);
    float4 v = xr[threadIdx.x];
    float s  = v.x + v.y + v.z + v.w;
    float sq = v.x*v.x + v.y*v.y + v.z*v.z + v.w*v.w;
    s  = blockReduceSum256(s, sh);
    sq = blockReduceSum256(sq, sh);
    float mean = s * (1.0f / DD);
    float var  = sq * (1.0f / DD) - mean * mean;
    float rstd = rsqrtf(var + 1e-5f);
    float4 g  = ((const float4*)gamma)[threadIdx.x];
    float4 be = ((const float4*)beta)[threadIdx.x];
    float4 o;
    o.x = (v.x - mean) * rstd * g.x + be.x;
    o.y = (v.y - mean) * rstd * g.y + be.y;
    o.z = (v.z - mean) * rstd * g.z + be.z;
    o.w = (v.w - mean) * rstd * g.w + be.w;
    ((float4*)(g_xn + (long long)row * DD))[threadIdx.x] = o;
    float nq = o.x*o.x + o.y*o.y + o.z*o.z + o.w*o.w;
    nq = blockReduceSum256(nq, sh);
    if (threadIdx.x == 0)
        g_rnorm[row] = scale[0] / fmaxf(sqrtf(nq), 1e-12f);
}

// ---------------- kernel 2: mu unit columns, transposed ----------------------
__global__ void mu_kernel(const float* __restrict__ mu) {
    __shared__ float sh[8];
    int es = blockIdx.x;              // flattened (e,s): mu[d, es] at d*ES + es
    float vals[4];
    float sq = 0.0f;
    #pragma unroll
    for (int i = 0; i < 4; i++) {
        int d = threadIdx.x + i * 256;
        vals[i] = mu[(long long)d * ESL + es];
        sq += vals[i] * vals[i];
    }
    sq = blockReduceSum256(sq, sh);
    float inv = 1.0f / fmaxf(sqrtf(sq), 1e-12f);
    #pragma unroll
    for (int i = 0; i < 4; i++) {
        int d = threadIdx.x + i * 256;
        g_muuT[es * DD + d] = vals[i] * inv;
    }
}

// ---------------- kernel 3: logits = (xn * rnorm) @ muuT^T -------------------
// C[16384,256] = A[16384,1024] * B[256,1024]^T, alpha = rnorm[row]
__global__ void gemm_logits() {
    __shared__ float As[16][64];
    __shared__ float Bs[16][64];
    int row0 = blockIdx.y * 64, col0 = blockIdx.x * 64;
    int tid = threadIdx.x;
    int tx = tid & 15, ty = tid >> 4;
    int lrow = tid >> 2, kc4 = (tid & 3) << 2;
    float acc[4][4] = {};
    for (int k0 = 0; k0 < DD; k0 += 16) {
        float4 a  = *(const float4*)(g_xn   + (long long)(row0 + lrow) * DD + k0 + kc4);
        float4 bq = *(const float4*)(g_muuT + (long long)(col0 + lrow) * DD + k0 + kc4);
        As[kc4 + 0][lrow] = a.x;  As[kc4 + 1][lrow] = a.y;
        As[kc4 + 2][lrow] = a.z;  As[kc4 + 3][lrow] = a.w;
        Bs[kc4 + 0][lrow] = bq.x; Bs[kc4 + 1][lrow] = bq.y;
        Bs[kc4 + 2][lrow] = bq.z; Bs[kc4 + 3][lrow] = bq.w;
        __syncthreads();
        #pragma unroll
        for (int k = 0; k < 16; k++) {
            float4 ra = *(const float4*)&As[k][ty << 2];
            float4 rb = *(const float4*)&Bs[k][tx << 2];
            acc[0][0] += ra.x*rb.x; acc[0][1] += ra.x*rb.y; acc[0][2] += ra.x*rb.z; acc[0][3] += ra.x*rb.w;
            acc[1][0] += ra.y*rb.x; acc[1][1] += ra.y*rb.y; acc[1][2] += ra.y*rb.z; acc[1][3] += ra.y*rb.w;
            acc[2][0] += ra.z*rb.x; acc[2][1] += ra.z*rb.y; acc[2][2] += ra.z*rb.z; acc[2][3] += ra.z*rb.w;
            acc[3][0] += ra.w*rb.x; acc[3][1] += ra.w*rb.y; acc[3][2] += ra.w*rb.z; acc[3][3] += ra.w*rb.w;
        }
        __syncthreads();
    }
    #pragma unroll
    for (int i = 0; i < 4; i++) {
        int m = row0 + (ty << 2) + i;
        float al = g_rnorm[m];
        float4 o = make_float4(acc[i][0]*al, acc[i][1]*al, acc[i][2]*al, acc[i][3]*al);
        *(float4*)(g_logits + (long long)m * ESL + col0 + (tx << 2)) = o;
    }
}

// ---------------- kernel 4/5: softmaxes --------------------------------------
__global__ void softmax_combine() {
    __shared__ float sh[8];
    long long row = blockIdx.x;
    float v = g_logits[row * ESL + threadIdx.x];
    float m = blockReduceMax256(v, sh);
    float e = __expf(v - m);
    float s = blockReduceSum256(e, sh);
    g_combine[row * ESL + threadIdx.x] = e / s;
}

__global__ void softmax_dispatch() {
    __shared__ float sh[8];
    int b = blockIdx.x >> 8, es = blockIdx.x & 255;
    float v = g_logits[((long long)(b * NT + threadIdx.x)) * ESL + es];
    float m = blockReduceMax256(v, sh);
    float e = __expf(v - m);
    float s = blockReduceSum256(e, sh);
    g_dispT[(long long)blockIdx.x * NT + threadIdx.x] = e / s;
}

// ---------------- generic A[M,K] * B[K,N] GEMM with mode epilogue ------------
// MODE 1: slot_in  (z=batch b):  A=dispT[b] [256,256], B=xn[b] [256,1024]
//                                C scatter -> g_slotin[e][b*16+s][d]
// MODE 2: MLP1     (z=expert e): A=g_slotin[e] [1024,1024], B=w1[e] [1024,256]
//                                C = gelu(v + b1[e]) -> g_h[e]
// MODE 3: MLP2     (z=expert e): A=g_h[e] [1024,256], B=w2[e] [256,1024]
//                                C = v + b2[e], scatter -> g_slotout[b][e*16+s][d]
// MODE 0: out      (z=batch b):  A=combine[b] [256,256], B=g_slotout[b] [256,1024]
//                                C -> d_out[b]
template <int MODE>
__global__ void gemm_ab(const float* __restrict__ W,
                        const float* __restrict__ bias,
                        float* __restrict__ Cout,
                        int M, int N, int K) {
    int z = blockIdx.z;
    const float* A;
    const float* B;
    if (MODE == 1)      { A = g_dispT   + (long long)z * ESL * NT;  B = g_xn      + (long long)z * NT * DD; }
    else if (MODE == 2) { A = g_slotin  + (long long)z * 1024 * DD; B = W         + (long long)z * DD * HH; }
    else if (MODE == 3) { A = g_h       + (long long)z * 1024 * HH; B = W         + (long long)z * HH * DD; }
    else                { A = g_combine + (long long)z * NT * ESL;  B = g_slotout + (long long)z * ESL * DD; }

    __shared__ float As[16][64];
    __shared__ float Bs[16][64];
    int row0 = blockIdx.y * 64, col0 = blockIdx.x * 64;
    int tid = threadIdx.x;
    int tx = tid & 15, ty = tid >> 4;
    int arow = tid >> 2,  kc4 = (tid & 3) << 2;   // A loader: 64 rows x 16 k
    int bkr  = tid >> 4,  bc4 = (tid & 15) << 2;  // B loader: 16 k x 64 cols
    float acc[4][4] = {};
    for (int k0 = 0; k0 < K; k0 += 16) {
        float4 a  = *(const float4*)(A + (long long)(row0 + arow) * K + k0 + kc4);
        float4 bq = *(const float4*)(B + (long long)(k0 + bkr) * N + col0 + bc4);
        As[kc4 + 0][arow] = a.x; As[kc4 + 1][arow] = a.y;
        As[kc4 + 2][arow] = a.z; As[kc4 + 3][arow] = a.w;
        *(float4*)&Bs[bkr][bc4] = bq;
        __syncthreads();
        #pragma unroll
        for (int k = 0; k < 16; k++) {
            float4 ra = *(const float4*)&As[k][ty << 2];
            float4 rb = *(const float4*)&Bs[k][tx << 2];
            acc[0][0] += ra.x*rb.x; acc[0][1] += ra.x*rb.y; acc[0][2] += ra.x*rb.z; acc[0][3] += ra.x*rb.w;
            acc[1][0] += ra.y*rb.x; acc[1][1] += ra.y*rb.y; acc[1][2] += ra.y*rb.z; acc[1][3] += ra.y*rb.w;
            acc[2][0] += ra.z*rb.x; acc[2][1] += ra.z*rb.y; acc[2][2] += ra.z*rb.z; acc[2][3] += ra.z*rb.w;
            acc[3][0] += ra.w*rb.x; acc[3][1] += ra.w*rb.y; acc[3][2] += ra.w*rb.z; acc[3][3] += ra.w*rb.w;
        }
        __syncthreads();
    }
    int col = col0 + (tx << 2);
    #pragma unroll
    for (int i = 0; i < 4; i++) {
        int m = row0 + (ty << 2) + i;
        float4 o = make_float4(acc[i][0], acc[i][1], acc[i][2], acc[i][3]);
        if (MODE == 2) {
            float4 bb = *(const float4*)(bias + (long long)z * HH + col);
            o.x = gelu_f(o.x + bb.x); o.y = gelu_f(o.y + bb.y);
            o.z = gelu_f(o.z + bb.z); o.w = gelu_f(o.w + bb.w);
            *(float4*)(g_h + ((long long)z * 1024 + m) * HH + col) = o;
        } else if (MODE == 3) {
            float4 bb = *(const float4*)(bias + (long long)z * DD + col);
            o.x += bb.x; o.y += bb.y; o.z += bb.z; o.w += bb.w;
            int b = m >> 4, s = m & 15;
            *(float4*)(g_slotout + ((long long)b * ESL + z * SS + s) * DD + col) = o;
        } else if (MODE == 1) {
            int e = m >> 4, s = m & 15;
            *(float4*)(g_slotin + (((long long)e * BB + z) * SS + s) * DD + col) = o;
        } else {
            *(float4*)(Cout + ((long long)z * NT + m) * DD + col) = o;
        }
    }
}

// ---------------- launch -----------------------------------------------------
extern "C" void kernel_launch(void* const* d_in, const int* in_sizes, int n_in,
                              void* d_out, int out_size) {
    const float* x     = (const float*)d_in[0];
    const float* gamma = (const float*)d_in[1];
    const float* beta  = (const float*)d_in[2];
    const float* mu    = (const float*)d_in[3];
    const float* scale = (const float*)d_in[4];
    const float* w1    = (const float*)d_in[5];
    const float* b1    = (const float*)d_in[6];
    const float* w2    = (const float*)d_in[7];
    const float* b2    = (const float*)d_in[8];
    float* out = (float*)d_out;
    (void)in_sizes; (void)n_in; (void)out_size;

    ln_kernel<<<BNR, 256>>>(x, gamma, beta, scale);
    mu_kernel<<<ESL, 256>>>(mu);
    // logits: M=16384, N=256, K=1024
    gemm_logits<<<dim3(ESL / 64, BNR / 64), 256>>>();
    softmax_combine<<<BNR, 256>>>();
    softmax_dispatch<<<BB * ESL, 256>>>();
    // slot_in: per batch b, M=256(ES), N=1024(D), K=256(N tokens)
    gemm_ab<1><<<dim3(DD / 64, ESL / 64, BB), 256>>>(nullptr, nullptr, nullptr, ESL, DD, NT);
    // MLP1: per expert e, M=1024(B*S), N=256(H), K=1024(D)
    gemm_ab<2><<<dim3(HH / 64, 1024 / 64, EE), 256>>>(w1, b1, nullptr, 1024, HH, DD);
    // MLP2: per expert e, M=1024(B*S), N=1024(D), K=256(H)
    gemm_ab<3><<<dim3(DD / 64, 1024 / 64, EE), 256>>>(w2, b2, nullptr, 1024, DD, HH);
    // out: per batch b, M=256(N tokens), N=1024(D), K=256(ES)
    gemm_ab<0><<<dim3(DD / 64, NT / 64, BB), 256>>>(nullptr, nullptr, out, NT, DD, ESL);
}

// round 6
// speedup vs baseline: 2.5792x; 2.5792x over previous
#include <cuda_runtime.h>
#include <math.h>
#include <stdint.h>

// Problem dims
#define DD    1024
#define EE    16
#define SS    16
#define ESL   256
#define BB    64
#define NT    256
#define BNR   16384
#define HH    256

// ---------------- scratch (device globals) -----------------------------------
__device__ float g_xn[(long long)BNR * DD];            // [B*N, D]
__device__ float g_rnorm[BNR];
__device__ float g_muuN[DD * ESL];                     // mu_unit, natural [d][es]
__device__ float g_logits[(long long)BNR * ESL];
__device__ float g_dispT[(long long)BB * ESL * NT];    // [b][es][n]
__device__ float g_combine[(long long)BNR * ESL];      // [b][n][es]
__device__ float g_slotin[(long long)EE * 1024 * DD];  // [e][b*16+s][d]
__device__ float g_h[(long long)EE * 1024 * HH];       // [e][b*16+s][h]
__device__ float g_slotout[(long long)BB * ESL * DD];  // [b][es][d]

// ---------------- helpers -----------------------------------------------------
__device__ __forceinline__ uint32_t tf32r(float v) {
    uint32_t u; asm("cvt.rna.tf32.f32 %0, %1;" : "=r"(u) : "f"(v)); return u;
}
__device__ __forceinline__ void mma_tf32(float* c, const uint32_t* a, const uint32_t* b) {
    asm volatile(
        "mma.sync.aligned.m16n8k8.row.col.f32.tf32.tf32.f32 "
        "{%0,%1,%2,%3}, {%4,%5,%6,%7}, {%8,%9}, {%0,%1,%2,%3};"
        : "+f"(c[0]), "+f"(c[1]), "+f"(c[2]), "+f"(c[3])
        : "r"(a[0]), "r"(a[1]), "r"(a[2]), "r"(a[3]), "r"(b[0]), "r"(b[1]));
}
__device__ __forceinline__ float gelu_f(float v) {
    return 0.5f * v * (1.0f + erff(v * 0.70710678118654752f));
}

__device__ __forceinline__ float blockReduceSum256(float v, float* sh) {
    #pragma unroll
    for (int o = 16; o > 0; o >>= 1) v += __shfl_down_sync(0xffffffffu, v, o);
    int lane = threadIdx.x & 31, w = threadIdx.x >> 5;
    if (lane == 0) sh[w] = v;
    __syncthreads();
    if (w == 0) {
        float t = (lane < 8) ? sh[lane] : 0.0f;
        #pragma unroll
        for (int o = 4; o > 0; o >>= 1) t += __shfl_down_sync(0xffu, t, o);
        if (lane == 0) sh[0] = t;
    }
    __syncthreads();
    float r = sh[0];
    __syncthreads();
    return r;
}
__device__ __forceinline__ float blockReduceMax256(float v, float* sh) {
    #pragma unroll
    for (int o = 16; o > 0; o >>= 1) v = fmaxf(v, __shfl_down_sync(0xffffffffu, v, o));
    int lane = threadIdx.x & 31, w = threadIdx.x >> 5;
    if (lane == 0) sh[w] = v;
    __syncthreads();
    if (w == 0) {
        float t = (lane < 8) ? sh[lane] : -INFINITY;
        #pragma unroll
        for (int o = 4; o > 0; o >>= 1) t = fmaxf(t, __shfl_down_sync(0xffu, t, o));
        if (lane == 0) sh[0] = t;
    }
    __syncthreads();
    float r = sh[0];
    __syncthreads();
    return r;
}

// ---------------- LayerNorm + row inv-norm -----------------------------------
__global__ void ln_kernel(const float* __restrict__ x, const float* __restrict__ gamma,
                          const float* __restrict__ beta, const float* __restrict__ scale) {
    __shared__ float sh[8];
    int row = blockIdx.x;
    float4 v = ((const float4*)(x + (long long)row * DD))[threadIdx.x];
    float s  = v.x + v.y + v.z + v.w;
    float sq = v.x*v.x + v.y*v.y + v.z*v.z + v.w*v.w;
    s  = blockReduceSum256(s, sh);
    sq = blockReduceSum256(sq, sh);
    float mean = s * (1.0f / DD);
    float var  = sq * (1.0f / DD) - mean * mean;
    float rstd = rsqrtf(var + 1e-5f);
    float4 g  = ((const float4*)gamma)[threadIdx.x];
    float4 be = ((const float4*)beta)[threadIdx.x];
    float4 o;
    o.x = (v.x - mean) * rstd * g.x + be.x;
    o.y = (v.y - mean) * rstd * g.y + be.y;
    o.z = (v.z - mean) * rstd * g.z + be.z;
    o.w = (v.w - mean) * rstd * g.w + be.w;
    ((float4*)(g_xn + (long long)row * DD))[threadIdx.x] = o;
    float nq = o.x*o.x + o.y*o.y + o.z*o.z + o.w*o.w;
    nq = blockReduceSum256(nq, sh);
    if (threadIdx.x == 0)
        g_rnorm[row] = scale[0] / fmaxf(sqrtf(nq), 1e-12f);
}

// ---------------- mu unit columns (natural [d][es] layout) -------------------
__global__ void mu_kernel(const float* __restrict__ mu) {
    __shared__ float sh[8];
    int es = blockIdx.x;
    float vals[4];
    float sq = 0.0f;
    #pragma unroll
    for (int i = 0; i < 4; i++) {
        int d = threadIdx.x + i * 256;
        vals[i] = mu[(long long)d * ESL + es];
        sq += vals[i] * vals[i];
    }
    sq = blockReduceSum256(sq, sh);
    float inv = 1.0f / fmaxf(sqrtf(sq), 1e-12f);
    #pragma unroll
    for (int i = 0; i < 4; i++) {
        int d = threadIdx.x + i * 256;
        g_muuN[(long long)d * ESL + es] = vals[i] * inv;
    }
}

// ---------------- softmaxes ---------------------------------------------------
__global__ void softmax_combine() {
    __shared__ float sh[8];
    long long row = blockIdx.x;
    float v = g_logits[row * ESL + threadIdx.x];
    float m = blockReduceMax256(v, sh);
    float e = __expf(v - m);
    float s = blockReduceSum256(e, sh);
    g_combine[row * ESL + threadIdx.x] = e / s;
}

// dispatch softmax over tokens n, coalesced via shared transpose. grid (8, 64)
__global__ void softmax_dispatch2() {
    __shared__ float T[32][257];
    int b = blockIdx.y, es0 = blockIdx.x * 32;
    int tid = threadIdx.x, wid = tid >> 5, lane = tid & 31;
    #pragma unroll 4
    for (int i = 0; i < 32; i++) {
        int n = (i << 3) + wid;
        T[lane][n] = g_logits[((long long)(b * NT + n)) * ESL + es0 + lane];
    }
    __syncthreads();
    #pragma unroll
    for (int r = 0; r < 4; r++) {
        int es_l = (wid << 2) + r;
        float mx = -INFINITY;
        #pragma unroll
        for (int k = 0; k < 8; k++) mx = fmaxf(mx, T[es_l][lane + (k << 5)]);
        #pragma unroll
        for (int o = 16; o > 0; o >>= 1) mx = fmaxf(mx, __shfl_xor_sync(0xffffffffu, mx, o));
        float sm = 0.0f;
        #pragma unroll
        for (int k = 0; k < 8; k++) sm += __expf(T[es_l][lane + (k << 5)] - mx);
        #pragma unroll
        for (int o = 16; o > 0; o >>= 1) sm += __shfl_xor_sync(0xffffffffu, sm, o);
        float inv = 1.0f / sm;
        #pragma unroll
        for (int k = 0; k < 8; k++) {
            int n = lane + (k << 5);
            g_dispT[((long long)b * ESL + es0 + es_l) * NT + n] = __expf(T[es_l][n] - mx) * inv;
        }
    }
}

// ---------------- tf32 mma.sync GEMM -----------------------------------------
// C[128x128 tile] = A[M,K] * B[K,N], A row-major, B row-major [K][N].
// 256 thr = 8 warps (4m x 2n), warp tile 32x64, k-chunk 16.
// MODE 4: logits   MODE 1: slot_in   MODE 2: MLP1(gelu)  MODE 3: MLP2  MODE 0: out
template <int MODE>
__global__ void __launch_bounds__(256, 2) gemm_mma(const float* __restrict__ Wmat,
                                                   const float* __restrict__ bias,
                                                   float* __restrict__ Cout) {
    constexpr int KK = (MODE == 4 || MODE == 2) ? 1024 : 256;
    constexpr int NN = (MODE == 4 || MODE == 2) ? 256 : 1024;

    __shared__ uint32_t As[16][136];   // [k][m], pad 136 -> conflict-free frags
    __shared__ uint32_t Bs[16][136];   // [k][n]

    int tid = threadIdx.x, wid = tid >> 5, lane = tid & 31;
    int wm = wid >> 1, wn = wid & 1;
    int qq = lane >> 2, rr = lane & 3;
    int z = blockIdx.z;
    int row0 = blockIdx.y * 128, col0 = blockIdx.x * 128;

    const float* A;
    const float* B;
    if (MODE == 4)      { A = g_xn;                                 B = g_muuN; }
    else if (MODE == 1) { A = g_dispT   + (long long)z * ESL * NT;  B = g_xn      + (long long)z * NT * DD; }
    else if (MODE == 2) { A = g_slotin  + (long long)z * 1024 * DD; B = Wmat      + (long long)z * DD * HH; }
    else if (MODE == 3) { A = g_h       + (long long)z * 1024 * HH; B = Wmat      + (long long)z * HH * DD; }
    else                { A = g_combine + (long long)z * NT * ESL;  B = g_slotout + (long long)z * ESL * DD; }

    float acc[2][8][4];
    #pragma unroll
    for (int i = 0; i < 2; i++)
        #pragma unroll
        for (int j = 0; j < 8; j++)
            #pragma unroll
            for (int c = 0; c < 4; c++) acc[i][j][c] = 0.0f;

    for (int k0 = 0; k0 < KK; k0 += 16) {
        // A tile: 128 rows x 16 k  (2 float4 per thread, coalesced)
        #pragma unroll
        for (int i = 0; i < 2; i++) {
            int idx = tid + (i << 8);
            int r = idx >> 2, c4 = (idx & 3) << 2;
            float4 v = *(const float4*)(A + (long long)(row0 + r) * KK + k0 + c4);
            As[c4 + 0][r] = tf32r(v.x);
            As[c4 + 1][r] = tf32r(v.y);
            As[c4 + 2][r] = tf32r(v.z);
            As[c4 + 3][r] = tf32r(v.w);
        }
        // B tile: 16 k x 128 n  (2 float4 per thread, coalesced)
        #pragma unroll
        for (int i = 0; i < 2; i++) {
            int idx = tid + (i << 8);
            int kr = idx >> 5, nc4 = (idx & 31) << 2;
            float4 v = *(const float4*)(B + (long long)(k0 + kr) * NN + col0 + nc4);
            uint4 u = make_uint4(tf32r(v.x), tf32r(v.y), tf32r(v.z), tf32r(v.w));
            *(uint4*)&Bs[kr][nc4] = u;
        }
        __syncthreads();
        #pragma unroll
        for (int ks = 0; ks < 2; ks++) {
            int kb = ks << 3;
            uint32_t af[2][4], bf[8][2];
            #pragma unroll
            for (int mt = 0; mt < 2; mt++) {
                int m = wm * 32 + mt * 16 + qq;
                af[mt][0] = As[kb + rr][m];
                af[mt][1] = As[kb + rr][m + 8];
                af[mt][2] = As[kb + rr + 4][m];
                af[mt][3] = As[kb + rr + 4][m + 8];
            }
            #pragma unroll
            for (int nt = 0; nt < 8; nt++) {
                int n = wn * 64 + nt * 8 + qq;
                bf[nt][0] = Bs[kb + rr][n];
                bf[nt][1] = Bs[kb + rr + 4][n];
            }
            #pragma unroll
            for (int mt = 0; mt < 2; mt++)
                #pragma unroll
                for (int nt = 0; nt < 8; nt++)
                    mma_tf32(acc[mt][nt], af[mt], bf[nt]);
        }
        __syncthreads();
    }

    // ---------------- epilogue ----------------
    #pragma unroll
    for (int mt = 0; mt < 2; mt++) {
        int rbase = row0 + wm * 32 + mt * 16 + qq;
        #pragma unroll
        for (int h = 0; h < 2; h++) {       // h=0: rows +0 (c0,c1); h=1: rows +8 (c2,c3)
            int m = rbase + h * 8;
            float rn = (MODE == 4) ? g_rnorm[m] : 1.0f;
            #pragma unroll
            for (int nt = 0; nt < 8; nt++) {
                int col = col0 + wn * 64 + nt * 8 + (rr << 1);
                float2 o = make_float2(acc[mt][nt][h * 2], acc[mt][nt][h * 2 + 1]);
                if (MODE == 4) {
                    o.x *= rn; o.y *= rn;
                    *(float2*)(g_logits + (long long)m * ESL + col) = o;
                } else if (MODE == 1) {
                    int e = m >> 4, s = m & 15;
                    *(float2*)(g_slotin + ((long long)(e * BB + z) * SS + s) * DD + col) = o;
                } else if (MODE == 2) {
                    float2 bb = *(const float2*)(bias + (long long)z * HH + col);
                    o.x = gelu_f(o.x + bb.x); o.y = gelu_f(o.y + bb.y);
                    *(float2*)(g_h + ((long long)z * 1024 + m) * HH + col) = o;
                } else if (MODE == 3) {
                    float2 bb = *(const float2*)(bias + (long long)z * DD + col);
                    o.x += bb.x; o.y += bb.y;
                    int b = m >> 4, s = m & 15;
                    *(float2*)(g_slotout + ((long long)b * ESL + z * SS + s) * DD + col) = o;
                } else {
                    *(float2*)(Cout + ((long long)z * NT + m) * DD + col) = o;
                }
            }
        }
    }
}

// ---------------- launch ------------------------------------------------------
extern "C" void kernel_launch(void* const* d_in, const int* in_sizes, int n_in,
                              void* d_out, int out_size) {
    const float* x     = (const float*)d_in[0];
    const float* gamma = (const float*)d_in[1];
    const float* beta  = (const float*)d_in[2];
    const float* mu    = (const float*)d_in[3];
    const float* scale = (const float*)d_in[4];
    const float* w1    = (const float*)d_in[5];
    const float* b1    = (const float*)d_in[6];
    const float* w2    = (const float*)d_in[7];
    const float* b2    = (const float*)d_in[8];
    float* out = (float*)d_out;
    (void)in_sizes; (void)n_in; (void)out_size;

    ln_kernel<<<BNR, 256>>>(x, gamma, beta, scale);
    mu_kernel<<<ESL, 256>>>(mu);
    // logits: M=16384, N=256, K=1024
    gemm_mma<4><<<dim3(2, 128, 1), 256>>>(nullptr, nullptr, nullptr);
    softmax_combine<<<BNR, 256>>>();
    softmax_dispatch2<<<dim3(8, BB), 256>>>();
    // slot_in: per b, M=256(es), N=1024(d), K=256(n)
    gemm_mma<1><<<dim3(8, 2, BB), 256>>>(nullptr, nullptr, nullptr);
    // MLP1: per e, M=1024(b*s), N=256(h), K=1024(d)
    gemm_mma<2><<<dim3(2, 8, EE), 256>>>(w1, b1, nullptr);
    // MLP2: per e, M=1024(b*s), N=1024(d), K=256(h)
    gemm_mma<3><<<dim3(8, 8, EE), 256>>>(w2, b2, nullptr);
    // out: per b, M=256(n), N=1024(d), K=256(es)
    gemm_mma<0><<<dim3(8, 2, BB), 256>>>(nullptr, nullptr, out);
}

// round 7
// speedup vs baseline: 2.9782x; 1.1547x over previous
#include <cuda_runtime.h>
#include <math.h>
#include <stdint.h>

// Problem dims
#define DD    1024
#define EE    16
#define SS    16
#define ESL   256
#define BB    64
#define NT    256
#define BNR   16384
#define HH    256

// ---------------- scratch (device globals) -----------------------------------
__device__ float g_xn[(long long)BNR * DD];            // [B*N, D]
__device__ float g_rnorm[BNR];
__device__ float g_muuN[DD * ESL];                     // mu_unit, natural [d][es]
__device__ float g_logits[(long long)BNR * ESL];
__device__ float g_dispT[(long long)BB * ESL * NT];    // [b][es][n]
__device__ float g_combine[(long long)BNR * ESL];      // [b][n][es]
__device__ float g_slotin[(long long)EE * 1024 * DD];  // [e][b*16+s][d]
__device__ float g_h[(long long)EE * 1024 * HH];       // [e][b*16+s][h]
__device__ float g_slotout[(long long)BB * ESL * DD];  // [b][es][d]

// ---------------- helpers -----------------------------------------------------
__device__ __forceinline__ uint32_t tf32r(float v) {
    uint32_t u; asm("cvt.rna.tf32.f32 %0, %1;" : "=r"(u) : "f"(v)); return u;
}
__device__ __forceinline__ void mma_tf32(float* c, const uint32_t* a, const uint32_t* b) {
    asm volatile(
        "mma.sync.aligned.m16n8k8.row.col.f32.tf32.tf32.f32 "
        "{%0,%1,%2,%3}, {%4,%5,%6,%7}, {%8,%9}, {%0,%1,%2,%3};"
        : "+f"(c[0]), "+f"(c[1]), "+f"(c[2]), "+f"(c[3])
        : "r"(a[0]), "r"(a[1]), "r"(a[2]), "r"(a[3]), "r"(b[0]), "r"(b[1]));
}
__device__ __forceinline__ float gelu_f(float v) {
    return 0.5f * v * (1.0f + erff(v * 0.70710678118654752f));
}

__device__ __forceinline__ float blockReduceSum256(float v, float* sh) {
    #pragma unroll
    for (int o = 16; o > 0; o >>= 1) v += __shfl_down_sync(0xffffffffu, v, o);
    int lane = threadIdx.x & 31, w = threadIdx.x >> 5;
    if (lane == 0) sh[w] = v;
    __syncthreads();
    if (w == 0) {
        float t = (lane < 8) ? sh[lane] : 0.0f;
        #pragma unroll
        for (int o = 4; o > 0; o >>= 1) t += __shfl_down_sync(0xffu, t, o);
        if (lane == 0) sh[0] = t;
    }
    __syncthreads();
    float r = sh[0];
    __syncthreads();
    return r;
}
__device__ __forceinline__ float blockReduceMax256(float v, float* sh) {
    #pragma unroll
    for (int o = 16; o > 0; o >>= 1) v = fmaxf(v, __shfl_down_sync(0xffffffffu, v, o));
    int lane = threadIdx.x & 31, w = threadIdx.x >> 5;
    if (lane == 0) sh[w] = v;
    __syncthreads();
    if (w == 0) {
        float t = (lane < 8) ? sh[lane] : -INFINITY;
        #pragma unroll
        for (int o = 4; o > 0; o >>= 1) t = fmaxf(t, __shfl_down_sync(0xffu, t, o));
        if (lane == 0) sh[0] = t;
    }
    __syncthreads();
    float r = sh[0];
    __syncthreads();
    return r;
}

// ---------------- LayerNorm + row inv-norm -----------------------------------
__global__ void ln_kernel(const float* __restrict__ x, const float* __restrict__ gamma,
                          const float* __restrict__ beta, const float* __restrict__ scale) {
    __shared__ float sh[8];
    int row = blockIdx.x;
    float4 v = ((const float4*)(x + (long long)row * DD))[threadIdx.x];
    float s  = v.x + v.y + v.z + v.w;
    float sq = v.x*v.x + v.y*v.y + v.z*v.z + v.w*v.w;
    s  = blockReduceSum256(s, sh);
    sq = blockReduceSum256(sq, sh);
    float mean = s * (1.0f / DD);
    float var  = sq * (1.0f / DD) - mean * mean;
    float rstd = rsqrtf(var + 1e-5f);
    float4 g  = ((const float4*)gamma)[threadIdx.x];
    float4 be = ((const float4*)beta)[threadIdx.x];
    float4 o;
    o.x = (v.x - mean) * rstd * g.x + be.x;
    o.y = (v.y - mean) * rstd * g.y + be.y;
    o.z = (v.z - mean) * rstd * g.z + be.z;
    o.w = (v.w - mean) * rstd * g.w + be.w;
    ((float4*)(g_xn + (long long)row * DD))[threadIdx.x] = o;
    float nq = o.x*o.x + o.y*o.y + o.z*o.z + o.w*o.w;
    nq = blockReduceSum256(nq, sh);
    if (threadIdx.x == 0)
        g_rnorm[row] = scale[0] / fmaxf(sqrtf(nq), 1e-12f);
}

// ---------------- mu unit columns (natural [d][es] layout) -------------------
__global__ void mu_kernel(const float* __restrict__ mu) {
    __shared__ float sh[8];
    int es = blockIdx.x;
    float vals[4];
    float sq = 0.0f;
    #pragma unroll
    for (int i = 0; i < 4; i++) {
        int d = threadIdx.x + i * 256;
        vals[i] = mu[(long long)d * ESL + es];
        sq += vals[i] * vals[i];
    }
    sq = blockReduceSum256(sq, sh);
    float inv = 1.0f / fmaxf(sqrtf(sq), 1e-12f);
    #pragma unroll
    for (int i = 0; i < 4; i++) {
        int d = threadIdx.x + i * 256;
        g_muuN[(long long)d * ESL + es] = vals[i] * inv;
    }
}

// ---------------- softmaxes ---------------------------------------------------
__global__ void softmax_combine() {
    __shared__ float sh[8];
    long long row = blockIdx.x;
    float v = g_logits[row * ESL + threadIdx.x];
    float m = blockReduceMax256(v, sh);
    float e = __expf(v - m);
    float s = blockReduceSum256(e, sh);
    g_combine[row * ESL + threadIdx.x] = e / s;
}

// dispatch softmax over tokens n, coalesced via shared transpose. grid (8, 64)
__global__ void softmax_dispatch2() {
    __shared__ float T[32][257];
    int b = blockIdx.y, es0 = blockIdx.x * 32;
    int tid = threadIdx.x, wid = tid >> 5, lane = tid & 31;
    #pragma unroll 4
    for (int i = 0; i < 32; i++) {
        int n = (i << 3) + wid;
        T[lane][n] = g_logits[((long long)(b * NT + n)) * ESL + es0 + lane];
    }
    __syncthreads();
    #pragma unroll
    for (int r = 0; r < 4; r++) {
        int es_l = (wid << 2) + r;
        float mx = -INFINITY;
        #pragma unroll
        for (int k = 0; k < 8; k++) mx = fmaxf(mx, T[es_l][lane + (k << 5)]);
        #pragma unroll
        for (int o = 16; o > 0; o >>= 1) mx = fmaxf(mx, __shfl_xor_sync(0xffffffffu, mx, o));
        float sm = 0.0f;
        #pragma unroll
        for (int k = 0; k < 8; k++) sm += __expf(T[es_l][lane + (k << 5)] - mx);
        #pragma unroll
        for (int o = 16; o > 0; o >>= 1) sm += __shfl_xor_sync(0xffffffffu, sm, o);
        float inv = 1.0f / sm;
        #pragma unroll
        for (int k = 0; k < 8; k++) {
            int n = lane + (k << 5);
            g_dispT[((long long)b * ESL + es0 + es_l) * NT + n] = __expf(T[es_l][n] - mx) * inv;
        }
    }
}

// ---------------- tf32 mma.sync GEMM with register-prefetch pipelining -------
// C[128x128 tile] = A[M,K] * B[K,N], A row-major, B row-major [K][N].
// 256 thr = 8 warps (4m x 2n), warp tile 32x64, k-chunk 16.
// MODE 4: logits   MODE 1: slot_in   MODE 2: MLP1(gelu)  MODE 3: MLP2  MODE 0: out
template <int MODE>
__global__ void __launch_bounds__(256, 2) gemm_mma(const float* __restrict__ Wmat,
                                                   const float* __restrict__ bias,
                                                   float* __restrict__ Cout) {
    constexpr int KK = (MODE == 4 || MODE == 2) ? 1024 : 256;
    constexpr int NN = (MODE == 4 || MODE == 2) ? 256 : 1024;
    constexpr int NC = KK / 16;

    __shared__ uint32_t As[16][136];   // [k][m], pad 136 -> conflict-free frags
    __shared__ uint32_t Bs[16][136];   // [k][n]

    int tid = threadIdx.x, wid = tid >> 5, lane = tid & 31;
    int wm = wid >> 1, wn = wid & 1;
    int qq = lane >> 2, rr = lane & 3;
    int z = blockIdx.z;
    int row0 = blockIdx.y * 128, col0 = blockIdx.x * 128;

    const float* A;
    const float* B;
    if (MODE == 4)      { A = g_xn;                                 B = g_muuN; }
    else if (MODE == 1) { A = g_dispT   + (long long)z * ESL * NT;  B = g_xn      + (long long)z * NT * DD; }
    else if (MODE == 2) { A = g_slotin  + (long long)z * 1024 * DD; B = Wmat      + (long long)z * DD * HH; }
    else if (MODE == 3) { A = g_h       + (long long)z * 1024 * HH; B = Wmat      + (long long)z * HH * DD; }
    else                { A = g_combine + (long long)z * NT * ESL;  B = g_slotout + (long long)z * ESL * DD; }

    // per-thread load coordinates
    const int ar0 = tid >> 2,            ac4 = (tid & 3) << 2;            // A: rows, k-col
    const int ar1 = (tid + 256) >> 2;                                     // second A row
    const int bk0 = tid >> 5,            bc4 = (tid & 31) << 2;           // B: k-row, col
    const int bk1 = (tid + 256) >> 5;

    const float* Aptr0 = A + (long long)(row0 + ar0) * KK + ac4;
    const float* Aptr1 = A + (long long)(row0 + ar1) * KK + ac4;
    const float* Bptr0 = B + (long long)bk0 * NN + col0 + bc4;
    const float* Bptr1 = B + (long long)bk1 * NN + col0 + bc4;

    float acc[2][8][4];
    #pragma unroll
    for (int i = 0; i < 2; i++)
        #pragma unroll
        for (int j = 0; j < 8; j++)
            #pragma unroll
            for (int c = 0; c < 4; c++) acc[i][j][c] = 0.0f;

    // prefetch chunk 0 into registers
    float4 pa0 = *(const float4*)(Aptr0);
    float4 pa1 = *(const float4*)(Aptr1);
    float4 pb0 = *(const float4*)(Bptr0);
    float4 pb1 = *(const float4*)(Bptr1);

    for (int kc = 0; kc < NC; kc++) {
        // ---- store current chunk (regs -> SMEM, tf32-rounded) ----
        As[ac4 + 0][ar0] = tf32r(pa0.x); As[ac4 + 1][ar0] = tf32r(pa0.y);
        As[ac4 + 2][ar0] = tf32r(pa0.z); As[ac4 + 3][ar0] = tf32r(pa0.w);
        As[ac4 + 0][ar1] = tf32r(pa1.x); As[ac4 + 1][ar1] = tf32r(pa1.y);
        As[ac4 + 2][ar1] = tf32r(pa1.z); As[ac4 + 3][ar1] = tf32r(pa1.w);
        {
            uint4 u0 = make_uint4(tf32r(pb0.x), tf32r(pb0.y), tf32r(pb0.z), tf32r(pb0.w));
            uint4 u1 = make_uint4(tf32r(pb1.x), tf32r(pb1.y), tf32r(pb1.z), tf32r(pb1.w));
            *(uint4*)&Bs[bk0][bc4] = u0;
            *(uint4*)&Bs[bk1][bc4] = u1;
        }
        __syncthreads();

        // ---- prefetch next chunk (LDG latency overlaps MMAs below) ----
        if (kc + 1 < NC) {
            int ko = (kc + 1) << 4;
            pa0 = *(const float4*)(Aptr0 + ko);
            pa1 = *(const float4*)(Aptr1 + ko);
            pb0 = *(const float4*)(Bptr0 + (long long)ko * NN);
            pb1 = *(const float4*)(Bptr1 + (long long)ko * NN);
        }

        // ---- compute ----
        #pragma unroll
        for (int ks = 0; ks < 2; ks++) {
            int kb = ks << 3;
            uint32_t af[2][4], bf[8][2];
            #pragma unroll
            for (int mt = 0; mt < 2; mt++) {
                int m = wm * 32 + mt * 16 + qq;
                af[mt][0] = As[kb + rr][m];
                af[mt][1] = As[kb + rr][m + 8];
                af[mt][2] = As[kb + rr + 4][m];
                af[mt][3] = As[kb + rr + 4][m + 8];
            }
            #pragma unroll
            for (int nt = 0; nt < 8; nt++) {
                int n = wn * 64 + nt * 8 + qq;
                bf[nt][0] = Bs[kb + rr][n];
                bf[nt][1] = Bs[kb + rr + 4][n];
            }
            #pragma unroll
            for (int mt = 0; mt < 2; mt++)
                #pragma unroll
                for (int nt = 0; nt < 8; nt++)
                    mma_tf32(acc[mt][nt], af[mt], bf[nt]);
        }
        __syncthreads();
    }

    // ---------------- epilogue ----------------
    #pragma unroll
    for (int mt = 0; mt < 2; mt++) {
        int rbase = row0 + wm * 32 + mt * 16 + qq;
        #pragma unroll
        for (int h = 0; h < 2; h++) {       // h=0: rows +0 (c0,c1); h=1: rows +8 (c2,c3)
            int m = rbase + h * 8;
            float rn = (MODE == 4) ? g_rnorm[m] : 1.0f;
            #pragma unroll
            for (int nt = 0; nt < 8; nt++) {
                int col = col0 + wn * 64 + nt * 8 + (rr << 1);
                float2 o = make_float2(acc[mt][nt][h * 2], acc[mt][nt][h * 2 + 1]);
                if (MODE == 4) {
                    o.x *= rn; o.y *= rn;
                    *(float2*)(g_logits + (long long)m * ESL + col) = o;
                } else if (MODE == 1) {
                    int e = m >> 4, s = m & 15;
                    *(float2*)(g_slotin + ((long long)(e * BB + z) * SS + s) * DD + col) = o;
                } else if (MODE == 2) {
                    float2 bb = *(const float2*)(bias + (long long)z * HH + col);
                    o.x = gelu_f(o.x + bb.x); o.y = gelu_f(o.y + bb.y);
                    *(float2*)(g_h + ((long long)z * 1024 + m) * HH + col) = o;
                } else if (MODE == 3) {
                    float2 bb = *(const float2*)(bias + (long long)z * DD + col);
                    o.x += bb.x; o.y += bb.y;
                    int b = m >> 4, s = m & 15;
                    *(float2*)(g_slotout + ((long long)b * ESL + z * SS + s) * DD + col) = o;
                } else {
                    *(float2*)(Cout + ((long long)z * NT + m) * DD + col) = o;
                }
            }
        }
    }
}

// ---------------- launch ------------------------------------------------------
extern "C" void kernel_launch(void* const* d_in, const int* in_sizes, int n_in,
                              void* d_out, int out_size) {
    const float* x     = (const float*)d_in[0];
    const float* gamma = (const float*)d_in[1];
    const float* beta  = (const float*)d_in[2];
    const float* mu    = (const float*)d_in[3];
    const float* scale = (const float*)d_in[4];
    const float* w1    = (const float*)d_in[5];
    const float* b1    = (const float*)d_in[6];
    const float* w2    = (const float*)d_in[7];
    const float* b2    = (const float*)d_in[8];
    float* out = (float*)d_out;
    (void)in_sizes; (void)n_in; (void)out_size;

    ln_kernel<<<BNR, 256>>>(x, gamma, beta, scale);
    mu_kernel<<<ESL, 256>>>(mu);
    // logits: M=16384, N=256, K=1024
    gemm_mma<4><<<dim3(2, 128, 1), 256>>>(nullptr, nullptr, nullptr);
    softmax_combine<<<BNR, 256>>>();
    softmax_dispatch2<<<dim3(8, BB), 256>>>();
    // slot_in: per b, M=256(es), N=1024(d), K=256(n)
    gemm_mma<1><<<dim3(8, 2, BB), 256>>>(nullptr, nullptr, nullptr);
    // MLP1: per e, M=1024(b*s), N=256(h), K=1024(d)
    gemm_mma<2><<<dim3(2, 8, EE), 256>>>(w1, b1, nullptr);
    // MLP2: per e, M=1024(b*s), N=1024(d), K=256(h)
    gemm_mma<3><<<dim3(8, 8, EE), 256>>>(w2, b2, nullptr);
    // out: per b, M=256(n), N=1024(d), K=256(es)
    gemm_mma<0><<<dim3(8, 2, BB), 256>>>(nullptr, nullptr, out);
}

// round 8
// speedup vs baseline: 3.1228x; 1.0486x over previous
#include <cuda_runtime.h>
#include <math.h>
#include <stdint.h>

// Problem dims
#define DD    1024
#define EE    16
#define SS    16
#define ESL   256
#define BB    64
#define NT    256
#define BNR   16384
#define HH    256

// ---------------- scratch (device globals) -----------------------------------
__device__ float g_xn[(long long)BNR * DD];            // [B*N, D]
__device__ float g_rnorm[BNR];
__device__ float g_muuN[DD * ESL];                     // mu_unit, natural [d][es]
__device__ float g_logits[(long long)BNR * ESL];
__device__ float g_dispT[(long long)BB * ESL * NT];    // [b][es][n]
__device__ float g_combine[(long long)BNR * ESL];      // [b][n][es]
__device__ float g_slotin[(long long)EE * 1024 * DD];  // [e][b*16+s][d]
__device__ float g_h[(long long)EE * 1024 * HH];       // [e][b*16+s][h]
__device__ float g_slotout[(long long)BB * ESL * DD];  // [b][es][d]

// ---------------- helpers -----------------------------------------------------
__device__ __forceinline__ uint32_t tf32r(float v) {
    uint32_t u; asm("cvt.rna.tf32.f32 %0, %1;" : "=r"(u) : "f"(v)); return u;
}
__device__ __forceinline__ void mma_tf32(float* c, const uint32_t* a, const uint32_t* b) {
    asm volatile(
        "mma.sync.aligned.m16n8k8.row.col.f32.tf32.tf32.f32 "
        "{%0,%1,%2,%3}, {%4,%5,%6,%7}, {%8,%9}, {%0,%1,%2,%3};"
        : "+f"(c[0]), "+f"(c[1]), "+f"(c[2]), "+f"(c[3])
        : "r"(a[0]), "r"(a[1]), "r"(a[2]), "r"(a[3]), "r"(b[0]), "r"(b[1]));
}
__device__ __forceinline__ float gelu_f(float v) {
    return 0.5f * v * (1.0f + erff(v * 0.70710678118654752f));
}
__device__ __forceinline__ float warpSum(float v) {
    #pragma unroll
    for (int o = 16; o > 0; o >>= 1) v += __shfl_xor_sync(0xffffffffu, v, o);
    return v;
}
__device__ __forceinline__ float warpMax(float v) {
    #pragma unroll
    for (int o = 16; o > 0; o >>= 1) v = fmaxf(v, __shfl_xor_sync(0xffffffffu, v, o));
    return v;
}
__device__ __forceinline__ float blockReduceSum256(float v, float* sh) {
    #pragma unroll
    for (int o = 16; o > 0; o >>= 1) v += __shfl_down_sync(0xffffffffu, v, o);
    int lane = threadIdx.x & 31, w = threadIdx.x >> 5;
    if (lane == 0) sh[w] = v;
    __syncthreads();
    if (w == 0) {
        float t = (lane < 8) ? sh[lane] : 0.0f;
        #pragma unroll
        for (int o = 4; o > 0; o >>= 1) t += __shfl_down_sync(0xffu, t, o);
        if (lane == 0) sh[0] = t;
    }
    __syncthreads();
    float r = sh[0];
    __syncthreads();
    return r;
}

// ---------------- LayerNorm + row inv-norm (warp-per-row, no barriers) -------
__global__ void ln_warp(const float* __restrict__ x, const float* __restrict__ gamma,
                        const float* __restrict__ beta, const float* __restrict__ scale) {
    int w = threadIdx.x >> 5, lane = threadIdx.x & 31;
    int row = blockIdx.x * 8 + w;
    const float4* xr = (const float4*)(x + (long long)row * DD);
    float4 v[8];
    float s = 0.0f, sq = 0.0f;
    #pragma unroll
    for (int i = 0; i < 8; i++) {
        v[i] = xr[lane + (i << 5)];
        s  += v[i].x + v[i].y + v[i].z + v[i].w;
        sq += v[i].x*v[i].x + v[i].y*v[i].y + v[i].z*v[i].z + v[i].w*v[i].w;
    }
    s = warpSum(s); sq = warpSum(sq);
    float mean = s * (1.0f / DD);
    float var  = sq * (1.0f / DD) - mean * mean;
    float rstd = rsqrtf(var + 1e-5f);
    float nq = 0.0f;
    float4* xo = (float4*)(g_xn + (long long)row * DD);
    #pragma unroll
    for (int i = 0; i < 8; i++) {
        float4 g  = ((const float4*)gamma)[lane + (i << 5)];
        float4 be = ((const float4*)beta)[lane + (i << 5)];
        float4 o;
        o.x = (v[i].x - mean) * rstd * g.x + be.x;
        o.y = (v[i].y - mean) * rstd * g.y + be.y;
        o.z = (v[i].z - mean) * rstd * g.z + be.z;
        o.w = (v[i].w - mean) * rstd * g.w + be.w;
        xo[lane + (i << 5)] = o;
        nq += o.x*o.x + o.y*o.y + o.z*o.z + o.w*o.w;
    }
    nq = warpSum(nq);
    if (lane == 0)
        g_rnorm[row] = scale[0] / fmaxf(sqrtf(nq), 1e-12f);
}

// ---------------- mu unit columns (natural [d][es] layout) -------------------
__global__ void mu_kernel(const float* __restrict__ mu) {
    __shared__ float sh[8];
    int es = blockIdx.x;
    float vals[4];
    float sq = 0.0f;
    #pragma unroll
    for (int i = 0; i < 4; i++) {
        int d = threadIdx.x + i * 256;
        vals[i] = mu[(long long)d * ESL + es];
        sq += vals[i] * vals[i];
    }
    sq = blockReduceSum256(sq, sh);
    float inv = 1.0f / fmaxf(sqrtf(sq), 1e-12f);
    #pragma unroll
    for (int i = 0; i < 4; i++) {
        int d = threadIdx.x + i * 256;
        g_muuN[(long long)d * ESL + es] = vals[i] * inv;
    }
}

// ---------------- combine softmax (warp-per-row, no barriers) ----------------
__global__ void softmax_combine_warp() {
    int w = threadIdx.x >> 5, lane = threadIdx.x & 31;
    long long row = blockIdx.x * 8 + w;
    const float4* lr = (const float4*)(g_logits + row * ESL);
    float4 v[2];
    float mx = -INFINITY;
    #pragma unroll
    for (int i = 0; i < 2; i++) {
        v[i] = lr[lane + (i << 5)];
        mx = fmaxf(mx, fmaxf(fmaxf(v[i].x, v[i].y), fmaxf(v[i].z, v[i].w)));
    }
    mx = warpMax(mx);
    float sm = 0.0f;
    #pragma unroll
    for (int i = 0; i < 2; i++) {
        v[i].x = __expf(v[i].x - mx); v[i].y = __expf(v[i].y - mx);
        v[i].z = __expf(v[i].z - mx); v[i].w = __expf(v[i].w - mx);
        sm += v[i].x + v[i].y + v[i].z + v[i].w;
    }
    sm = warpSum(sm);
    float inv = 1.0f / sm;
    float4* cr = (float4*)(g_combine + row * ESL);
    #pragma unroll
    for (int i = 0; i < 2; i++) {
        v[i].x *= inv; v[i].y *= inv; v[i].z *= inv; v[i].w *= inv;
        cr[lane + (i << 5)] = v[i];
    }
}

// dispatch softmax over tokens n, coalesced via shared transpose. grid (8, 64)
__global__ void softmax_dispatch2() {
    __shared__ float T[32][257];
    int b = blockIdx.y, es0 = blockIdx.x * 32;
    int tid = threadIdx.x, wid = tid >> 5, lane = tid & 31;
    #pragma unroll 4
    for (int i = 0; i < 32; i++) {
        int n = (i << 3) + wid;
        T[lane][n] = g_logits[((long long)(b * NT + n)) * ESL + es0 + lane];
    }
    __syncthreads();
    #pragma unroll
    for (int r = 0; r < 4; r++) {
        int es_l = (wid << 2) + r;
        float mx = -INFINITY;
        #pragma unroll
        for (int k = 0; k < 8; k++) mx = fmaxf(mx, T[es_l][lane + (k << 5)]);
        mx = warpMax(mx);
        float sm = 0.0f;
        #pragma unroll
        for (int k = 0; k < 8; k++) sm += __expf(T[es_l][lane + (k << 5)] - mx);
        sm = warpSum(sm);
        float inv = 1.0f / sm;
        #pragma unroll
        for (int k = 0; k < 8; k++) {
            int n = lane + (k << 5);
            g_dispT[((long long)b * ESL + es0 + es_l) * NT + n] = __expf(T[es_l][n] - mx) * inv;
        }
    }
}

// ---------------- tf32 mma.sync GEMM: double-buffered, single sync/chunk -----
// C[128x128 tile] = A[M,K] * B[K,N], A row-major, B row-major [K][N].
// 256 thr = 8 warps (4m x 2n), warp tile 32x64, k-chunk 16.
// MODE 4: logits   MODE 1: slot_in   MODE 2: MLP1(gelu)  MODE 3: MLP2  MODE 0: out
template <int MODE>
__global__ void __launch_bounds__(256, 2) gemm_mma(const float* __restrict__ Wmat,
                                                   const float* __restrict__ bias,
                                                   float* __restrict__ Cout) {
    constexpr int KK = (MODE == 4 || MODE == 2) ? 1024 : 256;
    constexpr int NN = (MODE == 4 || MODE == 2) ? 256 : 1024;
    constexpr int NC = KK / 16;

    __shared__ uint32_t As[2][16][136];
    __shared__ uint32_t Bs[2][16][136];

    int tid = threadIdx.x, wid = tid >> 5, lane = tid & 31;
    int wm = wid >> 1, wn = wid & 1;
    int qq = lane >> 2, rr = lane & 3;
    int z = blockIdx.z;
    int row0 = blockIdx.y * 128, col0 = blockIdx.x * 128;

    const float* A;
    const float* B;
    if (MODE == 4)      { A = g_xn;                                 B = g_muuN; }
    else if (MODE == 1) { A = g_dispT   + (long long)z * ESL * NT;  B = g_xn      + (long long)z * NT * DD; }
    else if (MODE == 2) { A = g_slotin  + (long long)z * 1024 * DD; B = Wmat      + (long long)z * DD * HH; }
    else if (MODE == 3) { A = g_h       + (long long)z * 1024 * HH; B = Wmat      + (long long)z * HH * DD; }
    else                { A = g_combine + (long long)z * NT * ESL;  B = g_slotout + (long long)z * ESL * DD; }

    // per-thread load coordinates
    const int ar0 = tid >> 2,  ac4 = (tid & 3) << 2;
    const int ar1 = (tid + 256) >> 2;
    const int bk0 = tid >> 5,  bc4 = (tid & 31) << 2;
    const int bk1 = (tid + 256) >> 5;

    const float* Aptr0 = A + (long long)(row0 + ar0) * KK + ac4;
    const float* Aptr1 = A + (long long)(row0 + ar1) * KK + ac4;
    const float* Bptr0 = B + (long long)bk0 * NN + col0 + bc4;
    const float* Bptr1 = B + (long long)bk1 * NN + col0 + bc4;

    float acc[2][8][4];
    #pragma unroll
    for (int i = 0; i < 2; i++)
        #pragma unroll
        for (int j = 0; j < 8; j++)
            #pragma unroll
            for (int c = 0; c < 4; c++) acc[i][j][c] = 0.0f;

    // prefetch + store chunk 0 into buffer 0
    {
        float4 a0 = *(const float4*)(Aptr0);
        float4 a1 = *(const float4*)(Aptr1);
        float4 b0 = *(const float4*)(Bptr0);
        float4 b1 = *(const float4*)(Bptr1);
        As[0][ac4 + 0][ar0] = tf32r(a0.x); As[0][ac4 + 1][ar0] = tf32r(a0.y);
        As[0][ac4 + 2][ar0] = tf32r(a0.z); As[0][ac4 + 3][ar0] = tf32r(a0.w);
        As[0][ac4 + 0][ar1] = tf32r(a1.x); As[0][ac4 + 1][ar1] = tf32r(a1.y);
        As[0][ac4 + 2][ar1] = tf32r(a1.z); As[0][ac4 + 3][ar1] = tf32r(a1.w);
        uint4 u0 = make_uint4(tf32r(b0.x), tf32r(b0.y), tf32r(b0.z), tf32r(b0.w));
        uint4 u1 = make_uint4(tf32r(b1.x), tf32r(b1.y), tf32r(b1.z), tf32r(b1.w));
        *(uint4*)&Bs[0][bk0][bc4] = u0;
        *(uint4*)&Bs[0][bk1][bc4] = u1;
    }
    __syncthreads();

    for (int kc = 0; kc < NC; kc++) {
        int cur = kc & 1;
        float4 pa0, pa1, pb0, pb1;
        bool more = (kc + 1 < NC);
        if (more) {
            int ko = (kc + 1) << 4;
            pa0 = *(const float4*)(Aptr0 + ko);
            pa1 = *(const float4*)(Aptr1 + ko);
            pb0 = *(const float4*)(Bptr0 + (long long)ko * NN);
            pb1 = *(const float4*)(Bptr1 + (long long)ko * NN);
        }

        // ---- compute on buffer cur (overlaps the LDGs above) ----
        #pragma unroll
        for (int ks = 0; ks < 2; ks++) {
            int kb = ks << 3;
            uint32_t af[2][4], bf[8][2];
            #pragma unroll
            for (int mt = 0; mt < 2; mt++) {
                int m = wm * 32 + mt * 16 + qq;
                af[mt][0] = As[cur][kb + rr][m];
                af[mt][1] = As[cur][kb + rr][m + 8];
                af[mt][2] = As[cur][kb + rr + 4][m];
                af[mt][3] = As[cur][kb + rr + 4][m + 8];
            }
            #pragma unroll
            for (int nt = 0; nt < 8; nt++) {
                int n = wn * 64 + nt * 8 + qq;
                bf[nt][0] = Bs[cur][kb + rr][n];
                bf[nt][1] = Bs[cur][kb + rr + 4][n];
            }
            #pragma unroll
            for (int mt = 0; mt < 2; mt++)
                #pragma unroll
                for (int nt = 0; nt < 8; nt++)
                    mma_tf32(acc[mt][nt], af[mt], bf[nt]);
        }

        // ---- store next chunk into the other buffer, then single sync ----
        if (more) {
            int nxt = cur ^ 1;
            As[nxt][ac4 + 0][ar0] = tf32r(pa0.x); As[nxt][ac4 + 1][ar0] = tf32r(pa0.y);
            As[nxt][ac4 + 2][ar0] = tf32r(pa0.z); As[nxt][ac4 + 3][ar0] = tf32r(pa0.w);
            As[nxt][ac4 + 0][ar1] = tf32r(pa1.x); As[nxt][ac4 + 1][ar1] = tf32r(pa1.y);
            As[nxt][ac4 + 2][ar1] = tf32r(pa1.z); As[nxt][ac4 + 3][ar1] = tf32r(pa1.w);
            uint4 u0 = make_uint4(tf32r(pb0.x), tf32r(pb0.y), tf32r(pb0.z), tf32r(pb0.w));
            uint4 u1 = make_uint4(tf32r(pb1.x), tf32r(pb1.y), tf32r(pb1.z), tf32r(pb1.w));
            *(uint4*)&Bs[nxt][bk0][bc4] = u0;
            *(uint4*)&Bs[nxt][bk1][bc4] = u1;
            __syncthreads();
        }
    }

    // ---------------- epilogue ----------------
    #pragma unroll
    for (int mt = 0; mt < 2; mt++) {
        int rbase = row0 + wm * 32 + mt * 16 + qq;
        #pragma unroll
        for (int h = 0; h < 2; h++) {
            int m = rbase + h * 8;
            float rn = (MODE == 4) ? g_rnorm[m] : 1.0f;
            #pragma unroll
            for (int nt = 0; nt < 8; nt++) {
                int col = col0 + wn * 64 + nt * 8 + (rr << 1);
                float2 o = make_float2(acc[mt][nt][h * 2], acc[mt][nt][h * 2 + 1]);
                if (MODE == 4) {
                    o.x *= rn; o.y *= rn;
                    *(float2*)(g_logits + (long long)m * ESL + col) = o;
                } else if (MODE == 1) {
                    int e = m >> 4, s = m & 15;
                    *(float2*)(g_slotin + ((long long)(e * BB + z) * SS + s) * DD + col) = o;
                } else if (MODE == 2) {
                    float2 bb = *(const float2*)(bias + (long long)z * HH + col);
                    o.x = gelu_f(o.x + bb.x); o.y = gelu_f(o.y + bb.y);
                    *(float2*)(g_h + ((long long)z * 1024 + m) * HH + col) = o;
                } else if (MODE == 3) {
                    float2 bb = *(const float2*)(bias + (long long)z * DD + col);
                    o.x += bb.x; o.y += bb.y;
                    int b = m >> 4, s = m & 15;
                    *(float2*)(g_slotout + ((long long)b * ESL + z * SS + s) * DD + col) = o;
                } else {
                    *(float2*)(Cout + ((long long)z * NT + m) * DD + col) = o;
                }
            }
        }
    }
}

// ---------------- launch ------------------------------------------------------
extern "C" void kernel_launch(void* const* d_in, const int* in_sizes, int n_in,
                              void* d_out, int out_size) {
    const float* x     = (const float*)d_in[0];
    const float* gamma = (const float*)d_in[1];
    const float* beta  = (const float*)d_in[2];
    const float* mu    = (const float*)d_in[3];
    const float* scale = (const float*)d_in[4];
    const float* w1    = (const float*)d_in[5];
    const float* b1    = (const float*)d_in[6];
    const float* w2    = (const float*)d_in[7];
    const float* b2    = (const float*)d_in[8];
    float* out = (float*)d_out;
    (void)in_sizes; (void)n_in; (void)out_size;

    ln_warp<<<BNR / 8, 256>>>(x, gamma, beta, scale);
    mu_kernel<<<ESL, 256>>>(mu);
    // logits: M=16384, N=256, K=1024
    gemm_mma<4><<<dim3(2, 128, 1), 256>>>(nullptr, nullptr, nullptr);
    softmax_combine_warp<<<BNR / 8, 256>>>();
    softmax_dispatch2<<<dim3(8, BB), 256>>>();
    // slot_in: per b, M=256(es), N=1024(d), K=256(n)
    gemm_mma<1><<<dim3(8, 2, BB), 256>>>(nullptr, nullptr, nullptr);
    // MLP1: per e, M=1024(b*s), N=256(h), K=1024(d)
    gemm_mma<2><<<dim3(2, 8, EE), 256>>>(w1, b1, nullptr);
    // MLP2: per e, M=1024(b*s), N=1024(d), K=256(h)
    gemm_mma<3><<<dim3(8, 8, EE), 256>>>(w2, b2, nullptr);
    // out: per b, M=256(n), N=1024(d), K=256(es)
    gemm_mma<0><<<dim3(8, 2, BB), 256>>>(nullptr, nullptr, out);
}

// round 9
// speedup vs baseline: 5.0747x; 1.6250x over previous
#include <cuda_runtime.h>
#include <cuda_fp16.h>
#include <math.h>
#include <stdint.h>

// Problem dims
#define DD    1024
#define EE    16
#define SS    16
#define ESL   256
#define BB    64
#define NT    256
#define BNR   16384
#define HH    256

// ---------------- scratch (device globals) -----------------------------------
__device__ __half g_xnh[(long long)BNR * DD];             // [B*N, D]
__device__ float  g_rnorm[BNR];
__device__ __half g_muuN[DD * ESL];                       // [d][es]
__device__ __half g_logitsh[(long long)BNR * ESL];
__device__ __half g_dispTh[(long long)BB * ESL * NT];     // [b][es][n]
__device__ __half g_combineh[(long long)BNR * ESL];       // [b][n][es]
__device__ __half g_slotinh[(long long)EE * 1024 * DD];   // [e][b*16+s][d]
__device__ __half g_hh[(long long)EE * 1024 * HH];        // [e][b*16+s][h]
__device__ __half g_slotouth[(long long)BB * ESL * DD];   // [b][es][d]
__device__ __half g_w1h[(long long)EE * DD * HH];
__device__ __half g_w2h[(long long)EE * HH * DD];

// ---------------- helpers -----------------------------------------------------
__device__ __forceinline__ uint32_t f2h2(float a, float b) {
    __half2 t = __floats2half2_rn(a, b);
    return *(uint32_t*)&t;
}
__device__ __forceinline__ void mma_f16(float* c, const uint32_t* a, const uint32_t* b) {
    asm volatile(
        "mma.sync.aligned.m16n8k16.row.col.f32.f16.f16.f32 "
        "{%0,%1,%2,%3}, {%4,%5,%6,%7}, {%8,%9}, {%0,%1,%2,%3};"
        : "+f"(c[0]), "+f"(c[1]), "+f"(c[2]), "+f"(c[3])
        : "r"(a[0]), "r"(a[1]), "r"(a[2]), "r"(a[3]), "r"(b[0]), "r"(b[1]));
}
__device__ __forceinline__ float gelu_f(float v) {
    return 0.5f * v * (1.0f + erff(v * 0.70710678118654752f));
}
__device__ __forceinline__ float warpSum(float v) {
    #pragma unroll
    for (int o = 16; o > 0; o >>= 1) v += __shfl_xor_sync(0xffffffffu, v, o);
    return v;
}
__device__ __forceinline__ float warpMax(float v) {
    #pragma unroll
    for (int o = 16; o > 0; o >>= 1) v = fmaxf(v, __shfl_xor_sync(0xffffffffu, v, o));
    return v;
}
__device__ __forceinline__ float blockReduceSum256(float v, float* sh) {
    #pragma unroll
    for (int o = 16; o > 0; o >>= 1) v += __shfl_down_sync(0xffffffffu, v, o);
    int lane = threadIdx.x & 31, w = threadIdx.x >> 5;
    if (lane == 0) sh[w] = v;
    __syncthreads();
    if (w == 0) {
        float t = (lane < 8) ? sh[lane] : 0.0f;
        #pragma unroll
        for (int o = 4; o > 0; o >>= 1) t += __shfl_down_sync(0xffu, t, o);
        if (lane == 0) sh[0] = t;
    }
    __syncthreads();
    float r = sh[0];
    __syncthreads();
    return r;
}

// ---------------- f32 -> f16 bulk convert -------------------------------------
__global__ void f2h_kernel(const float* __restrict__ in, __half* __restrict__ out) {
    int i = blockIdx.x * blockDim.x + threadIdx.x;
    float4 v = ((const float4*)in)[i];
    ((uint2*)out)[i] = make_uint2(f2h2(v.x, v.y), f2h2(v.z, v.w));
}

// ---------------- LayerNorm + row inv-norm (warp-per-row) ---------------------
__global__ void ln_warp(const float* __restrict__ x, const float* __restrict__ gamma,
                        const float* __restrict__ beta, const float* __restrict__ scale) {
    int w = threadIdx.x >> 5, lane = threadIdx.x & 31;
    int row = blockIdx.x * 8 + w;
    const float4* xr = (const float4*)(x + (long long)row * DD);
    float4 v[8];
    float s = 0.0f, sq = 0.0f;
    #pragma unroll
    for (int i = 0; i < 8; i++) {
        v[i] = xr[lane + (i << 5)];
        s  += v[i].x + v[i].y + v[i].z + v[i].w;
        sq += v[i].x*v[i].x + v[i].y*v[i].y + v[i].z*v[i].z + v[i].w*v[i].w;
    }
    s = warpSum(s); sq = warpSum(sq);
    float mean = s * (1.0f / DD);
    float var  = sq * (1.0f / DD) - mean * mean;
    float rstd = rsqrtf(var + 1e-5f);
    float nq = 0.0f;
    uint2* xo = (uint2*)(g_xnh + (long long)row * DD);
    #pragma unroll
    for (int i = 0; i < 8; i++) {
        float4 g  = ((const float4*)gamma)[lane + (i << 5)];
        float4 be = ((const float4*)beta)[lane + (i << 5)];
        float4 o;
        o.x = (v[i].x - mean) * rstd * g.x + be.x;
        o.y = (v[i].y - mean) * rstd * g.y + be.y;
        o.z = (v[i].z - mean) * rstd * g.z + be.z;
        o.w = (v[i].w - mean) * rstd * g.w + be.w;
        xo[lane + (i << 5)] = make_uint2(f2h2(o.x, o.y), f2h2(o.z, o.w));
        nq += o.x*o.x + o.y*o.y + o.z*o.z + o.w*o.w;
    }
    nq = warpSum(nq);
    if (lane == 0)
        g_rnorm[row] = scale[0] / fmaxf(sqrtf(nq), 1e-12f);
}

// ---------------- mu unit columns ([d][es], half) -----------------------------
__global__ void mu_kernel(const float* __restrict__ mu) {
    __shared__ float sh[8];
    int es = blockIdx.x;
    float vals[4];
    float sq = 0.0f;
    #pragma unroll
    for (int i = 0; i < 4; i++) {
        int d = threadIdx.x + i * 256;
        vals[i] = mu[(long long)d * ESL + es];
        sq += vals[i] * vals[i];
    }
    sq = blockReduceSum256(sq, sh);
    float inv = 1.0f / fmaxf(sqrtf(sq), 1e-12f);
    #pragma unroll
    for (int i = 0; i < 4; i++) {
        int d = threadIdx.x + i * 256;
        g_muuN[(long long)d * ESL + es] = __float2half_rn(vals[i] * inv);
    }
}

// ---------------- combine softmax (warp-per-row) ------------------------------
__global__ void softmax_combine_warp() {
    int w = threadIdx.x >> 5, lane = threadIdx.x & 31;
    long long row = blockIdx.x * 8 + w;
    const uint2* lr = (const uint2*)(g_logitsh + row * ESL);
    float4 v[2];
    float mx = -INFINITY;
    #pragma unroll
    for (int i = 0; i < 2; i++) {
        uint2 raw = lr[lane + (i << 5)];
        float2 f0 = __half22float2(*(__half2*)&raw.x);
        float2 f1 = __half22float2(*(__half2*)&raw.y);
        v[i] = make_float4(f0.x, f0.y, f1.x, f1.y);
        mx = fmaxf(mx, fmaxf(fmaxf(v[i].x, v[i].y), fmaxf(v[i].z, v[i].w)));
    }
    mx = warpMax(mx);
    float sm = 0.0f;
    #pragma unroll
    for (int i = 0; i < 2; i++) {
        v[i].x = __expf(v[i].x - mx); v[i].y = __expf(v[i].y - mx);
        v[i].z = __expf(v[i].z - mx); v[i].w = __expf(v[i].w - mx);
        sm += v[i].x + v[i].y + v[i].z + v[i].w;
    }
    sm = warpSum(sm);
    float inv = 1.0f / sm;
    uint2* cr = (uint2*)(g_combineh + row * ESL);
    #pragma unroll
    for (int i = 0; i < 2; i++)
        cr[lane + (i << 5)] = make_uint2(f2h2(v[i].x * inv, v[i].y * inv),
                                         f2h2(v[i].z * inv, v[i].w * inv));
}

// dispatch softmax over tokens n, via shared transpose. grid (8, 64)
__global__ void softmax_dispatch2() {
    __shared__ float T[32][257];
    int b = blockIdx.y, es0 = blockIdx.x * 32;
    int tid = threadIdx.x, wid = tid >> 5, lane = tid & 31;
    #pragma unroll 4
    for (int i = 0; i < 32; i++) {
        int n = (i << 3) + wid;
        T[lane][n] = __half2float(g_logitsh[((long long)(b * NT + n)) * ESL + es0 + lane]);
    }
    __syncthreads();
    #pragma unroll
    for (int r = 0; r < 4; r++) {
        int es_l = (wid << 2) + r;
        float mx = -INFINITY;
        #pragma unroll
        for (int k = 0; k < 8; k++) mx = fmaxf(mx, T[es_l][lane + (k << 5)]);
        mx = warpMax(mx);
        float sm = 0.0f;
        #pragma unroll
        for (int k = 0; k < 8; k++) sm += __expf(T[es_l][lane + (k << 5)] - mx);
        sm = warpSum(sm);
        float inv = 1.0f / sm;
        #pragma unroll
        for (int k = 0; k < 8; k++) {
            int n = lane + (k << 5);
            g_dispTh[((long long)b * ESL + es0 + es_l) * NT + n] =
                __float2half_rn(__expf(T[es_l][n] - mx) * inv);
        }
    }
}

// ---------------- fp16 mma.sync GEMM: k32 chunks, double-buffered -------------
// C[128x128 tile] = A[M,K] * B[K,N], A row-major, B row-major [K][N], both fp16.
// 256 thr = 8 warps (4m x 2n), warp tile 32x64.
// MODE 4: logits   MODE 1: slot_in   MODE 2: MLP1(gelu)  MODE 3: MLP2  MODE 0: out
template <int MODE>
__global__ void __launch_bounds__(256, 2) gemm_mma(const float* __restrict__ bias,
                                                   float* __restrict__ Cout) {
    constexpr int KK = (MODE == 4 || MODE == 2) ? 1024 : 256;
    constexpr int NN = (MODE == 4 || MODE == 2) ? 256 : 1024;
    constexpr int NC = KK / 32;

    // word [kp][m] = half2(A[m][2kp], A[m][2kp+1]); stride 138 -> conflict-free STS
    __shared__ uint32_t As[2][16][138];
    // word [kp][n] = half2(B[2kp][n], B[2kp+1][n])
    __shared__ uint32_t Bs[2][16][136];

    int tid = threadIdx.x, wid = tid >> 5, lane = tid & 31;
    int wm = wid >> 1, wn = wid & 1;
    int qq = lane >> 2, rr = lane & 3;
    int z = blockIdx.z;
    int row0 = blockIdx.y * 128, col0 = blockIdx.x * 128;

    const __half* A;
    const __half* B;
    if (MODE == 4)      { A = g_xnh;                                B = g_muuN; }
    else if (MODE == 1) { A = g_dispTh   + (long long)z * ESL * NT; B = g_xnh       + (long long)z * NT * DD; }
    else if (MODE == 2) { A = g_slotinh  + (long long)z * 1024 * DD;B = g_w1h       + (long long)z * DD * HH; }
    else if (MODE == 3) { A = g_hh       + (long long)z * 1024 * HH;B = g_w2h       + (long long)z * HH * DD; }
    else                { A = g_combineh + (long long)z * NT * ESL; B = g_slotouth  + (long long)z * ESL * DD; }

    // loader coords
    const int ar = tid >> 3, aq = tid & 7;      // A: rows ar+32i, k-quad aq (4 halves)
    const int bw = tid >> 5, ng = tid & 31;     // B: kp2 = bw+8i, n-group ng

    const __half* ApA = A + (long long)(row0 + ar) * KK + (aq << 2);
    const __half* BpB = B + col0 + (ng << 2);

    float acc[2][8][4];
    #pragma unroll
    for (int i = 0; i < 2; i++)
        #pragma unroll
        for (int j = 0; j < 8; j++)
            #pragma unroll
            for (int c = 0; c < 4; c++) acc[i][j][c] = 0.0f;

    uint2 pa[4], pbl[2], pbh[2];
    // prefetch chunk 0
    #pragma unroll
    for (int i = 0; i < 4; i++)
        pa[i] = *(const uint2*)(ApA + (long long)(32 * i) * KK);
    #pragma unroll
    for (int i = 0; i < 2; i++) {
        int krow = 2 * (bw + 8 * i);
        pbl[i] = *(const uint2*)(BpB + (long long)krow * NN);
        pbh[i] = *(const uint2*)(BpB + (long long)(krow + 1) * NN);
    }
    // store chunk 0 -> buffer 0
    #pragma unroll
    for (int i = 0; i < 4; i++) {
        As[0][2 * aq][ar + 32 * i]     = pa[i].x;
        As[0][2 * aq + 1][ar + 32 * i] = pa[i].y;
    }
    #pragma unroll
    for (int i = 0; i < 2; i++) {
        int kp2 = bw + 8 * i;
        uint32_t w0 = __byte_perm(pbl[i].x, pbh[i].x, 0x5410);
        uint32_t w1 = __byte_perm(pbl[i].x, pbh[i].x, 0x7632);
        uint32_t w2 = __byte_perm(pbl[i].y, pbh[i].y, 0x5410);
        uint32_t w3 = __byte_perm(pbl[i].y, pbh[i].y, 0x7632);
        *(uint4*)&Bs[0][kp2][ng << 2] = make_uint4(w0, w1, w2, w3);
    }
    __syncthreads();

    for (int kc = 0; kc < NC; kc++) {
        int cur = kc & 1;
        bool more = (kc + 1 < NC);
        if (more) {
            int ko = (kc + 1) << 5;
            #pragma unroll
            for (int i = 0; i < 4; i++)
                pa[i] = *(const uint2*)(ApA + (long long)(32 * i) * KK + ko);
            #pragma unroll
            for (int i = 0; i < 2; i++) {
                int krow = ko + 2 * (bw + 8 * i);
                pbl[i] = *(const uint2*)(BpB + (long long)krow * NN);
                pbh[i] = *(const uint2*)(BpB + (long long)(krow + 1) * NN);
            }
        }

        // compute on buffer cur (two k16 mma steps)
        #pragma unroll
        for (int ks = 0; ks < 2; ks++) {
            int k8 = ks << 3;
            uint32_t af[2][4], bf[8][2];
            #pragma unroll
            for (int mt = 0; mt < 2; mt++) {
                int m = wm * 32 + mt * 16 + qq;
                af[mt][0] = As[cur][k8 + rr][m];
                af[mt][1] = As[cur][k8 + rr][m + 8];
                af[mt][2] = As[cur][k8 + rr + 4][m];
                af[mt][3] = As[cur][k8 + rr + 4][m + 8];
            }
            #pragma unroll
            for (int nt = 0; nt < 8; nt++) {
                int n = wn * 64 + nt * 8 + qq;
                bf[nt][0] = Bs[cur][k8 + rr][n];
                bf[nt][1] = Bs[cur][k8 + rr + 4][n];
            }
            #pragma unroll
            for (int mt = 0; mt < 2; mt++)
                #pragma unroll
                for (int nt = 0; nt < 8; nt++)
                    mma_f16(acc[mt][nt], af[mt], bf[nt]);
        }

        if (more) {
            int nxt = cur ^ 1;
            #pragma unroll
            for (int i = 0; i < 4; i++) {
                As[nxt][2 * aq][ar + 32 * i]     = pa[i].x;
                As[nxt][2 * aq + 1][ar + 32 * i] = pa[i].y;
            }
            #pragma unroll
            for (int i = 0; i < 2; i++) {
                int kp2 = bw + 8 * i;
                uint32_t w0 = __byte_perm(pbl[i].x, pbh[i].x, 0x5410);
                uint32_t w1 = __byte_perm(pbl[i].x, pbh[i].x, 0x7632);
                uint32_t w2 = __byte_perm(pbl[i].y, pbh[i].y, 0x5410);
                uint32_t w3 = __byte_perm(pbl[i].y, pbh[i].y, 0x7632);
                *(uint4*)&Bs[nxt][kp2][ng << 2] = make_uint4(w0, w1, w2, w3);
            }
            __syncthreads();
        }
    }

    // ---------------- epilogue ----------------
    #pragma unroll
    for (int mt = 0; mt < 2; mt++) {
        int rbase = row0 + wm * 32 + mt * 16 + qq;
        #pragma unroll
        for (int h = 0; h < 2; h++) {
            int m = rbase + h * 8;
            float rn = (MODE == 4) ? g_rnorm[m] : 1.0f;
            #pragma unroll
            for (int nt = 0; nt < 8; nt++) {
                int col = col0 + wn * 64 + nt * 8 + (rr << 1);
                float ox = acc[mt][nt][h * 2], oy = acc[mt][nt][h * 2 + 1];
                if (MODE == 4) {
                    *(uint32_t*)(g_logitsh + (long long)m * ESL + col) = f2h2(ox * rn, oy * rn);
                } else if (MODE == 1) {
                    int e = m >> 4, s = m & 15;
                    *(uint32_t*)(g_slotinh + ((long long)(e * BB + z) * SS + s) * DD + col) = f2h2(ox, oy);
                } else if (MODE == 2) {
                    float2 bb = *(const float2*)(bias + (long long)z * HH + col);
                    *(uint32_t*)(g_hh + ((long long)z * 1024 + m) * HH + col) =
                        f2h2(gelu_f(ox + bb.x), gelu_f(oy + bb.y));
                } else if (MODE == 3) {
                    float2 bb = *(const float2*)(bias + (long long)z * DD + col);
                    int b = m >> 4, s = m & 15;
                    *(uint32_t*)(g_slotouth + ((long long)b * ESL + z * SS + s) * DD + col) =
                        f2h2(ox + bb.x, oy + bb.y);
                } else {
                    *(float2*)(Cout + ((long long)z * NT + m) * DD + col) = make_float2(ox, oy);
                }
            }
        }
    }
}

// ---------------- launch ------------------------------------------------------
extern "C" void kernel_launch(void* const* d_in, const int* in_sizes, int n_in,
                              void* d_out, int out_size) {
    const float* x     = (const float*)d_in[0];
    const float* gamma = (const float*)d_in[1];
    const float* beta  = (const float*)d_in[2];
    const float* mu    = (const float*)d_in[3];
    const float* scale = (const float*)d_in[4];
    const float* w1    = (const float*)d_in[5];
    const float* b1    = (const float*)d_in[6];
    const float* w2    = (const float*)d_in[7];
    const float* b2    = (const float*)d_in[8];
    float* out = (float*)d_out;
    (void)in_sizes; (void)n_in; (void)out_size;

    void *p_w1h, *p_w2h;
    cudaGetSymbolAddress(&p_w1h, g_w1h);
    cudaGetSymbolAddress(&p_w2h, g_w2h);

    ln_warp<<<BNR / 8, 256>>>(x, gamma, beta, scale);
    mu_kernel<<<ESL, 256>>>(mu);
    f2h_kernel<<<(EE * DD * HH) / 4 / 256, 256>>>(w1, (__half*)p_w1h);
    f2h_kernel<<<(EE * HH * DD) / 4 / 256, 256>>>(w2, (__half*)p_w2h);
    // logits: M=16384, N=256, K=1024
    gemm_mma<4><<<dim3(2, 128, 1), 256>>>(nullptr, nullptr);
    softmax_combine_warp<<<BNR / 8, 256>>>();
    softmax_dispatch2<<<dim3(8, BB), 256>>>();
    // slot_in: per b, M=256(es), N=1024(d), K=256(n)
    gemm_mma<1><<<dim3(8, 2, BB), 256>>>(nullptr, nullptr);
    // MLP1: per e, M=1024(b*s), N=256(h), K=1024(d)
    gemm_mma<2><<<dim3(2, 8, EE), 256>>>(b1, nullptr);
    // MLP2: per e, M=1024(b*s), N=1024(d), K=256(h)
    gemm_mma<3><<<dim3(8, 8, EE), 256>>>(b2, nullptr);
    // out: per b, M=256(n), N=1024(d), K=256(es)
    gemm_mma<0><<<dim3(8, 2, BB), 256>>>(nullptr, out);
}

// round 12
// speedup vs baseline: 5.0765x; 1.0004x over previous
#include <cuda_runtime.h>
#include <cuda_fp16.h>
#include <math.h>
#include <stdint.h>

// Problem dims
#define DD    1024
#define EE    16
#define SS    16
#define ESL   256
#define BB    64
#define NT    256
#define BNR   16384
#define HH    256

// ---------------- scratch (device globals) -----------------------------------
__device__ __half g_xnh[(long long)BNR * DD];             // [B*N, D]
__device__ float  g_rnorm[BNR];
__device__ __half g_muuN[DD * ESL];                       // [d][es]
__device__ __half g_logitsh[(long long)BNR * ESL];
__device__ __half g_dispTh[(long long)BB * ESL * NT];     // [b][es][n]
__device__ __half g_combineh[(long long)BNR * ESL];       // [b][n][es]
__device__ __half g_slotinh[(long long)EE * 1024 * DD];   // [e][b*16+s][d]
__device__ __half g_hh[(long long)EE * 1024 * HH];        // [e][b*16+s][h]
__device__ __half g_slotouth[(long long)BB * ESL * DD];   // [b][es][d]
__device__ __half g_w1h[(long long)EE * DD * HH];
__device__ __half g_w2h[(long long)EE * HH * DD];

// ---------------- helpers -----------------------------------------------------
__device__ __forceinline__ uint32_t f2h2(float a, float b) {
    __half2 t = __floats2half2_rn(a, b);
    return *(uint32_t*)&t;
}
__device__ __forceinline__ void mma_f16(float* c, const uint32_t* a, const uint32_t* b) {
    asm volatile(
        "mma.sync.aligned.m16n8k16.row.col.f32.f16.f16.f32 "
        "{%0,%1,%2,%3}, {%4,%5,%6,%7}, {%8,%9}, {%0,%1,%2,%3};"
        : "+f"(c[0]), "+f"(c[1]), "+f"(c[2]), "+f"(c[3])
        : "r"(a[0]), "r"(a[1]), "r"(a[2]), "r"(a[3]), "r"(b[0]), "r"(b[1]));
}
__device__ __forceinline__ void ldsm_x4(uint32_t& r0, uint32_t& r1, uint32_t& r2,
                                        uint32_t& r3, uint32_t addr) {
    asm volatile("ldmatrix.sync.aligned.m8n8.x4.shared.b16 {%0,%1,%2,%3}, [%4];"
                 : "=r"(r0), "=r"(r1), "=r"(r2), "=r"(r3) : "r"(addr));
}
__device__ __forceinline__ void ldsm_x4_t(uint32_t& r0, uint32_t& r1, uint32_t& r2,
                                          uint32_t& r3, uint32_t addr) {
    asm volatile("ldmatrix.sync.aligned.m8n8.x4.trans.shared.b16 {%0,%1,%2,%3}, [%4];"
                 : "=r"(r0), "=r"(r1), "=r"(r2), "=r"(r3) : "r"(addr));
}
__device__ __forceinline__ float gelu_f(float v) {
    return 0.5f * v * (1.0f + erff(v * 0.70710678118654752f));
}
__device__ __forceinline__ float warpSum(float v) {
    #pragma unroll
    for (int o = 16; o > 0; o >>= 1) v += __shfl_xor_sync(0xffffffffu, v, o);
    return v;
}
__device__ __forceinline__ float warpMax(float v) {
    #pragma unroll
    for (int o = 16; o > 0; o >>= 1) v = fmaxf(v, __shfl_xor_sync(0xffffffffu, v, o));
    return v;
}
__device__ __forceinline__ float blockReduceSum256(float v, float* sh) {
    #pragma unroll
    for (int o = 16; o > 0; o >>= 1) v += __shfl_down_sync(0xffffffffu, v, o);
    int lane = threadIdx.x & 31, w = threadIdx.x >> 5;
    if (lane == 0) sh[w] = v;
    __syncthreads();
    if (w == 0) {
        float t = (lane < 8) ? sh[lane] : 0.0f;
        #pragma unroll
        for (int o = 4; o > 0; o >>= 1) t += __shfl_down_sync(0xffu, t, o);
        if (lane == 0) sh[0] = t;
    }
    __syncthreads();
    float r = sh[0];
    __syncthreads();
    return r;
}

// ---------------- f32 -> f16 bulk convert (both weight tensors) ---------------
#define WQUADS (EE * DD * HH / 4)
__global__ void f2h_both(const float* __restrict__ w1, __half* __restrict__ o1,
                         const float* __restrict__ w2, __half* __restrict__ o2) {
    int i = blockIdx.x * blockDim.x + threadIdx.x;
    const float* in = (i < WQUADS) ? w1 : w2;
    __half* out = (i < WQUADS) ? o1 : o2;
    int j = (i < WQUADS) ? i : i - WQUADS;
    float4 v = ((const float4*)in)[j];
    ((uint2*)out)[j] = make_uint2(f2h2(v.x, v.y), f2h2(v.z, v.w));
}

// ---------------- LayerNorm + row inv-norm (warp-per-row) ---------------------
__global__ void ln_warp(const float* __restrict__ x, const float* __restrict__ gamma,
                        const float* __restrict__ beta, const float* __restrict__ scale) {
    int w = threadIdx.x >> 5, lane = threadIdx.x & 31;
    int row = blockIdx.x * 8 + w;
    const float4* xr = (const float4*)(x + (long long)row * DD);
    float4 v[8];
    float s = 0.0f, sq = 0.0f;
    #pragma unroll
    for (int i = 0; i < 8; i++) {
        v[i] = xr[lane + (i << 5)];
        s  += v[i].x + v[i].y + v[i].z + v[i].w;
        sq += v[i].x*v[i].x + v[i].y*v[i].y + v[i].z*v[i].z + v[i].w*v[i].w;
    }
    s = warpSum(s); sq = warpSum(sq);
    float mean = s * (1.0f / DD);
    float var  = sq * (1.0f / DD) - mean * mean;
    float rstd = rsqrtf(var + 1e-5f);
    float nq = 0.0f;
    uint2* xo = (uint2*)(g_xnh + (long long)row * DD);
    #pragma unroll
    for (int i = 0; i < 8; i++) {
        float4 g  = ((const float4*)gamma)[lane + (i << 5)];
        float4 be = ((const float4*)beta)[lane + (i << 5)];
        float4 o;
        o.x = (v[i].x - mean) * rstd * g.x + be.x;
        o.y = (v[i].y - mean) * rstd * g.y + be.y;
        o.z = (v[i].z - mean) * rstd * g.z + be.z;
        o.w = (v[i].w - mean) * rstd * g.w + be.w;
        xo[lane + (i << 5)] = make_uint2(f2h2(o.x, o.y), f2h2(o.z, o.w));
        nq += o.x*o.x + o.y*o.y + o.z*o.z + o.w*o.w;
    }
    nq = warpSum(nq);
    if (lane == 0)
        g_rnorm[row] = scale[0] / fmaxf(sqrtf(nq), 1e-12f);
}

// ---------------- mu unit columns ([d][es], half) -----------------------------
__global__ void mu_kernel(const float* __restrict__ mu) {
    __shared__ float sh[8];
    int es = blockIdx.x;
    float vals[4];
    float sq = 0.0f;
    #pragma unroll
    for (int i = 0; i < 4; i++) {
        int d = threadIdx.x + i * 256;
        vals[i] = mu[(long long)d * ESL + es];
        sq += vals[i] * vals[i];
    }
    sq = blockReduceSum256(sq, sh);
    float inv = 1.0f / fmaxf(sqrtf(sq), 1e-12f);
    #pragma unroll
    for (int i = 0; i < 4; i++) {
        int d = threadIdx.x + i * 256;
        g_muuN[(long long)d * ESL + es] = __float2half_rn(vals[i] * inv);
    }
}

// ---------------- combine softmax (warp-per-row) ------------------------------
__global__ void softmax_combine_warp() {
    int w = threadIdx.x >> 5, lane = threadIdx.x & 31;
    long long row = blockIdx.x * 8 + w;
    const uint2* lr = (const uint2*)(g_logitsh + row * ESL);
    float4 v[2];
    float mx = -INFINITY;
    #pragma unroll
    for (int i = 0; i < 2; i++) {
        uint2 raw = lr[lane + (i << 5)];
        float2 f0 = __half22float2(*(__half2*)&raw.x);
        float2 f1 = __half22float2(*(__half2*)&raw.y);
        v[i] = make_float4(f0.x, f0.y, f1.x, f1.y);
        mx = fmaxf(mx, fmaxf(fmaxf(v[i].x, v[i].y), fmaxf(v[i].z, v[i].w)));
    }
    mx = warpMax(mx);
    float sm = 0.0f;
    #pragma unroll
    for (int i = 0; i < 2; i++) {
        v[i].x = __expf(v[i].x - mx); v[i].y = __expf(v[i].y - mx);
        v[i].z = __expf(v[i].z - mx); v[i].w = __expf(v[i].w - mx);
        sm += v[i].x + v[i].y + v[i].z + v[i].w;
    }
    sm = warpSum(sm);
    float inv = 1.0f / sm;
    uint2* cr = (uint2*)(g_combineh + row * ESL);
    #pragma unroll
    for (int i = 0; i < 2; i++)
        cr[lane + (i << 5)] = make_uint2(f2h2(v[i].x * inv, v[i].y * inv),
                                         f2h2(v[i].z * inv, v[i].w * inv));
}

// dispatch softmax over tokens n, via shared transpose. grid (8, 64)
__global__ void softmax_dispatch2() {
    __shared__ float T[32][257];
    int b = blockIdx.y, es0 = blockIdx.x * 32;
    int tid = threadIdx.x, wid = tid >> 5, lane = tid & 31;
    #pragma unroll 4
    for (int i = 0; i < 32; i++) {
        int n = (i << 3) + wid;
        T[lane][n] = __half2float(g_logitsh[((long long)(b * NT + n)) * ESL + es0 + lane]);
    }
    __syncthreads();
    #pragma unroll
    for (int r = 0; r < 4; r++) {
        int es_l = (wid << 2) + r;
        float mx = -INFINITY;
        #pragma unroll
        for (int k = 0; k < 8; k++) mx = fmaxf(mx, T[es_l][lane + (k << 5)]);
        mx = warpMax(mx);
        float sm = 0.0f;
        #pragma unroll
        for (int k = 0; k < 8; k++) sm += __expf(T[es_l][lane + (k << 5)] - mx);
        sm = warpSum(sm);
        float inv = 1.0f / sm;
        #pragma unroll
        for (int k = 0; k < 8; k++) {
            int n = lane + (k << 5);
            g_dispTh[((long long)b * ESL + es0 + es_l) * NT + n] =
                __float2half_rn(__expf(T[es_l][n] - mx) * inv);
        }
    }
}

// ---------------- fp16 mma GEMM: ldmatrix fragments, k32 double-buffered ------
// C[128x128 tile] = A[M,K] * B[K,N], fp16 operands, f32 accum.
// A smem: [128 rows][80B stride] (64B data) -> conflict-free LDSM (no xor).
// B smem: [32 k-rows][256B], 16B-chunk xor (k&7) -> conflict-free LDSM.trans.
// 256 thr = 8 warps (4m x 2n), warp tile 32x64.
// MODE 4: logits   MODE 1: slot_in   MODE 2: MLP1(gelu)  MODE 3: MLP2  MODE 0: out
#define A_STRIDE 80
#define A_BYTES  (128 * A_STRIDE)
#define B_BYTES  (32 * 256)
template <int MODE>
__global__ void __launch_bounds__(256, 2) gemm_mma(const float* __restrict__ bias,
                                                   float* __restrict__ Cout) {
    constexpr int KK = (MODE == 4 || MODE == 2) ? 1024 : 256;
    constexpr int NN = (MODE == 4 || MODE == 2) ? 256 : 1024;
    constexpr int NC = KK / 32;

    __shared__ __align__(16) char As[2][A_BYTES];
    __shared__ __align__(16) char Bs[2][B_BYTES];

    int tid = threadIdx.x, wid = tid >> 5, lane = tid & 31;
    int wm = wid >> 1, wn = wid & 1;
    int qq = lane >> 2, rr = lane & 3;
    int z = blockIdx.z;
    int row0 = blockIdx.y * 128, col0 = blockIdx.x * 128;

    const __half* A;
    const __half* B;
    if (MODE == 4)      { A = g_xnh;                                B = g_muuN; }
    else if (MODE == 1) { A = g_dispTh   + (long long)z * ESL * NT; B = g_xnh       + (long long)z * NT * DD; }
    else if (MODE == 2) { A = g_slotinh  + (long long)z * 1024 * DD;B = g_w1h       + (long long)z * DD * HH; }
    else if (MODE == 3) { A = g_hh       + (long long)z * 1024 * HH;B = g_w2h       + (long long)z * HH * DD; }
    else                { A = g_combineh + (long long)z * NT * ESL; B = g_slotouth  + (long long)z * ESL * DD; }

    // loader coords: A thread -> row ar, chunk pair ac{0,2}; B -> k-row bk, chunk pair bc
    const int ar = tid >> 1, ac = (tid & 1) << 1;
    const int bk = tid >> 3, bc = (tid & 7) << 1;
    const __half* ApA = A + (long long)(row0 + ar) * KK + (ac << 3);
    const __half* BpB = B + (long long)bk * NN + col0 + (bc << 3);

    // A store offsets (no xor), B store offsets (chunk xor k&7)
    char* AsD0 = (char*)As + ar * A_STRIDE + ac * 16;
    const int bX0 = (bc ^ (bk & 7)) * 16, bX1 = ((bc + 1) ^ (bk & 7)) * 16;
    char* BsD = (char*)Bs + bk * 256;

    // LDSM base addresses (per-lane)
    const int a_row = wm * 32 + ((lane >> 3) & 1) * 8 + (lane & 7);
    const int a_ch  = lane >> 4;                    // 0/1 within k16
    const int b_k   = ((lane >> 3) & 1) * 8 + (lane & 7);
    const int b_ch  = lane >> 4;                    // 0/1 within n16 pair

    float acc[2][8][4];
    #pragma unroll
    for (int i = 0; i < 2; i++)
        #pragma unroll
        for (int j = 0; j < 8; j++)
            #pragma unroll
            for (int c = 0; c < 4; c++) acc[i][j][c] = 0.0f;

    uint4 pa0, pa1, pb0, pb1;
    // prefetch chunk 0
    pa0 = *(const uint4*)(ApA);
    pa1 = *(const uint4*)(ApA + 8);
    pb0 = *(const uint4*)(BpB);
    pb1 = *(const uint4*)(BpB + 8);
    *(uint4*)(AsD0)            = pa0;
    *(uint4*)(AsD0 + 16)       = pa1;
    *(uint4*)(BsD + bX0)       = pb0;
    *(uint4*)(BsD + bX1)       = pb1;
    __syncthreads();

    for (int kc = 0; kc < NC; kc++) {
        int cur = kc & 1;
        bool more = (kc + 1 < NC);
        if (more) {
            int ko = (kc + 1) << 5;
            pa0 = *(const uint4*)(ApA + ko);
            pa1 = *(const uint4*)(ApA + ko + 8);
            pb0 = *(const uint4*)(BpB + (long long)ko * NN);
            pb1 = *(const uint4*)(BpB + (long long)ko * NN + 8);
        }

        // compute on buffer cur: two k16 steps
        #pragma unroll
        for (int ks = 0; ks < 2; ks++) {
            uint32_t af[2][4], bf[8][2];
            #pragma unroll
            for (int mt = 0; mt < 2; mt++) {
                uint32_t addr = (uint32_t)__cvta_generic_to_shared(
                    As[cur] + (a_row + mt * 16) * A_STRIDE + ((ks << 1) + a_ch) * 16);
                ldsm_x4(af[mt][0], af[mt][1], af[mt][2], af[mt][3], addr);
            }
            #pragma unroll
            for (int ntp = 0; ntp < 4; ntp++) {
                int k = (ks << 4) + b_k;
                int c = (wn << 3) + (ntp << 1) + b_ch;
                uint32_t addr = (uint32_t)__cvta_generic_to_shared(
                    Bs[cur] + k * 256 + ((c ^ (k & 7)) << 4));
                ldsm_x4_t(bf[2 * ntp][0], bf[2 * ntp][1],
                          bf[2 * ntp + 1][0], bf[2 * ntp + 1][1], addr);
            }
            #pragma unroll
            for (int mt = 0; mt < 2; mt++)
                #pragma unroll
                for (int nt = 0; nt < 8; nt++)
                    mma_f16(acc[mt][nt], af[mt], bf[nt]);
        }

        if (more) {
            char* AsD = AsD0 + (cur ^ 1 ? (A_BYTES) : 0) - (cur ? 0 : 0);
            // (compute target buffer explicitly)
            char* AsN = (char*)As[cur ^ 1] + ar * A_STRIDE + ac * 16;
            char* BsN = (char*)Bs[cur ^ 1] + bk * 256;
            (void)AsD;
            *(uint4*)(AsN)      = pa0;
            *(uint4*)(AsN + 16) = pa1;
            *(uint4*)(BsN + bX0) = pb0;
            *(uint4*)(BsN + bX1) = pb1;
            __syncthreads();
        }
    }

    // ---------------- epilogue ----------------
    #pragma unroll
    for (int mt = 0; mt < 2; mt++) {
        int rbase = row0 + wm * 32 + mt * 16 + qq;
        #pragma unroll
        for (int h = 0; h < 2; h++) {
            int m = rbase + h * 8;
            float rn = (MODE == 4) ? g_rnorm[m] : 1.0f;
            #pragma unroll
            for (int nt = 0; nt < 8; nt++) {
                int col = col0 + wn * 64 + nt * 8 + (rr << 1);
                float ox = acc[mt][nt][h * 2], oy = acc[mt][nt][h * 2 + 1];
                if (MODE == 4) {
                    *(uint32_t*)(g_logitsh + (long long)m * ESL + col) = f2h2(ox * rn, oy * rn);
                } else if (MODE == 1) {
                    int e = m >> 4, s = m & 15;
                    *(uint32_t*)(g_slotinh + ((long long)(e * BB + z) * SS + s) * DD + col) = f2h2(ox, oy);
                } else if (MODE == 2) {
                    float2 bb = *(const float2*)(bias + (long long)z * HH + col);
                    *(uint32_t*)(g_hh + ((long long)z * 1024 + m) * HH + col) =
                        f2h2(gelu_f(ox + bb.x), gelu_f(oy + bb.y));
                } else if (MODE == 3) {
                    float2 bb = *(const float2*)(bias + (long long)z * DD + col);
                    int b = m >> 4, s = m & 15;
                    *(uint32_t*)(g_slotouth + ((long long)b * ESL + z * SS + s) * DD + col) =
                        f2h2(ox + bb.x, oy + bb.y);
                } else {
                    *(float2*)(Cout + ((long long)z * NT + m) * DD + col) = make_float2(ox, oy);
                }
            }
        }
    }
}

// ---------------- launch ------------------------------------------------------
extern "C" void kernel_launch(void* const* d_in, const int* in_sizes, int n_in,
                              void* d_out, int out_size) {
    const float* x     = (const float*)d_in[0];
    const float* gamma = (const float*)d_in[1];
    const float* beta  = (const float*)d_in[2];
    const float* mu    = (const float*)d_in[3];
    const float* scale = (const float*)d_in[4];
    const float* w1    = (const float*)d_in[5];
    const float* b1    = (const float*)d_in[6];
    const float* w2    = (const float*)d_in[7];
    const float* b2    = (const float*)d_in[8];
    float* out = (float*)d_out;
    (void)in_sizes; (void)n_in; (void)out_size;

    void *p_w1h, *p_w2h;
    cudaGetSymbolAddress(&p_w1h, g_w1h);
    cudaGetSymbolAddress(&p_w2h, g_w2h);

    ln_warp<<<BNR / 8, 256>>>(x, gamma, beta, scale);
    mu_kernel<<<ESL, 256>>>(mu);
    f2h_both<<<(2 * WQUADS) / 256, 256>>>(w1, (__half*)p_w1h, w2, (__half*)p_w2h);
    // logits: M=16384, N=256, K=1024
    gemm_mma<4><<<dim3(2, 128, 1), 256>>>(nullptr, nullptr);
    softmax_combine_warp<<<BNR / 8, 256>>>();
    softmax_dispatch2<<<dim3(8, BB), 256>>>();
    // slot_in: per b, M=256(es), N=1024(d), K=256(n)
    gemm_mma<1><<<dim3(8, 2, BB), 256>>>(nullptr, nullptr);
    // MLP1: per e, M=1024(b*s), N=256(h), K=1024(d)
    gemm_mma<2><<<dim3(2, 8, EE), 256>>>(b1, nullptr);
    // MLP2: per e, M=1024(b*s), N=1024(d), K=256(h)
    gemm_mma<3><<<dim3(8, 8, EE), 256>>>(b2, nullptr);
    // out: per b, M=256(n), N=1024(d), K=256(es)
    gemm_mma<0><<<dim3(8, 2, BB), 256>>>(nullptr, out);
}